// round 8
// baseline (speedup 1.0000x reference)
#include <cuda_runtime.h>
#include <cuda_bf16.h>
#include <mma.h>
#include <cstdint>

using namespace nvcuda;

// ---------------------------------------------------------------------------
// Dims (fixed): B=2, T=2048, HID=2048, H=16, DK=DV=128, W=4; rows = B*T = 4096
// Toolchain lowers to compute_103 PTX (no tcgen05). Stay sm_80-portable.
// GEMM: CTA 256x128, 8 warps of 64x64, 3-stage cp.async, 1 sync/chunk.
// ---------------------------------------------------------------------------

__device__ float g_q   [4096ll * 2048];   // NORMALIZED q
__device__ float g_k   [4096ll * 2048];   // NORMALIZED k
__device__ float g_v   [4096ll * 2048];
__device__ float g_v2  [4096ll * 2048];   // silu(conv(v))
__device__ float g_o   [4096ll * 2048];
__device__ float g_xg  [4096ll * 2048];
__device__ float g_beta [4096 * 16];
__device__ float g_decay[4096 * 16];

#define MELEM 4194304ll
#define OFF_Q   (0ll)
#define OFF_K   (1ll * MELEM)
#define OFF_V   (2ll * MELEM)
#define OFF_G   (3ll * MELEM)
#define OFF_W1  (4ll * MELEM)
#define OFF_WO  (6ll * MELEM)
#define OFF_W2  (7ll * MELEM)
__device__ __nv_bfloat16 g_wth[11ll * MELEM];
__device__ __nv_bfloat16 g_wtl[11ll * MELEM];

__device__ __nv_bfloat16 g_p0h[4096ll * 2048];
__device__ __nv_bfloat16 g_p0l[4096ll * 2048];
__device__ __nv_bfloat16 g_pqh[4096ll * 4096];
__device__ __nv_bfloat16 g_pql[4096ll * 4096];

__device__ __forceinline__ float sigmoidf_(float x) { return 1.f / (1.f + expf(-x)); }

__device__ __forceinline__ uint32_t smem_u32(const void* p) {
    uint32_t a;
    asm("{ .reg .u64 t; cvta.to.shared.u64 t, %1; cvt.u32.u64 %0, t; }" : "=r"(a) : "l"(p));
    return a;
}
__device__ __forceinline__ void cp16(uint32_t so, const void* g) {
    asm volatile("cp.async.cg.shared.global [%0], [%1], 16;" :: "r"(so), "l"(g));
}
__device__ __forceinline__ void cp4(uint32_t so, const void* g) {
    asm volatile("cp.async.ca.shared.global [%0], [%1], 4;" :: "r"(so), "l"(g));
}

__device__ __forceinline__ void split2(float x, float y, uint32_t& hu, uint32_t& lu) {
    __nv_bfloat16 hx = __float2bfloat16_rn(x), hy = __float2bfloat16_rn(y);
    __nv_bfloat16 lx = __float2bfloat16_rn(x - __bfloat162float(hx));
    __nv_bfloat16 ly = __float2bfloat16_rn(y - __bfloat162float(hy));
    __nv_bfloat162 h(hx, hy), l(lx, ly);
    hu = *(uint32_t*)&h;
    lu = *(uint32_t*)&l;
}
__device__ __forceinline__ void split4_store(
    float4 v, __nv_bfloat16* __restrict__ h, __nv_bfloat16* __restrict__ l, size_t i)
{
    uint2 hu, lu;
    split2(v.x, v.y, hu.x, lu.x);
    split2(v.z, v.w, hu.y, lu.y);
    *(uint2*)(h + i) = hu;
    *(uint2*)(l + i) = lu;
}

// ---------------------------------------------------------------------------
// Weight prep
// ---------------------------------------------------------------------------
struct PrepBatch { const float* W[5]; long long off[5]; };

__global__ void __launch_bounds__(256) prep_kernel(
    PrepBatch pb, __nv_bfloat16* __restrict__ Th, __nv_bfloat16* __restrict__ Tl,
    int N, int Kd)
{
    __shared__ float s[32][33];
    const float* W = pb.W[blockIdx.z];
    const long long base = pb.off[blockIdx.z];
    const int n0 = blockIdx.x * 32, k0 = blockIdx.y * 32;
    const int tid = threadIdx.x;
#pragma unroll
    for (int j = 0; j < 4; ++j) {
        int lin = tid + j * 256;
        int kk = lin >> 5, nn = lin & 31;
        s[kk][nn] = W[(size_t)(k0 + kk) * N + n0 + nn];
    }
    __syncthreads();
#pragma unroll
    for (int j = 0; j < 4; ++j) {
        int lin = tid + j * 256;
        int nn = lin >> 5, kk = lin & 31;
        float v = s[kk][nn];
        __nv_bfloat16 h = __float2bfloat16_rn(v);
        __nv_bfloat16 l = __float2bfloat16_rn(v - __bfloat162float(h));
        size_t o = (size_t)base + (size_t)(n0 + nn) * Kd + k0 + kk;
        Th[o] = h;
        Tl[o] = l;
    }
}

__global__ void __launch_bounds__(256) split_kernel(
    const float* __restrict__ s, __nv_bfloat16* __restrict__ h, __nv_bfloat16* __restrict__ l)
{
    size_t i = ((size_t)blockIdx.x * 256 + threadIdx.x) * 4;
    split4_store(*(const float4*)(s + i), h, l, i);
}

// ---------------------------------------------------------------------------
// Split-bf16 HMMA GEMM, CTA 256x128, warp 64x64, 3-stage, fused epilogues.
// ---------------------------------------------------------------------------
struct GB {
    const __nv_bfloat16* Ah[4]; const __nv_bfloat16* Al[4];
    const __nv_bfloat16* Bh[4]; const __nv_bfloat16* Bl[4];
    float* C[4];
    int epi[4];
    __nv_bfloat16* eh[4]; __nv_bfloat16* el[4];
    long long estride[4]; long long ecol[4];
    const float* vsrc; const float* bias;
};

#define STAGE 61440      // Ah 20480 | Al 20480 | Bh 10240 | Bl 10240
#define EPS 140

__global__ void __launch_bounds__(256, 1) gemm_cp(
    GB bt, int M, int N, int K)
{
    extern __shared__ __align__(16) char dsm[];
    __shared__ float sc[256];
    const int tid = threadIdx.x;
    const int wid = tid >> 5;
    const int lane = tid & 31;
    const int wm  = wid >> 1;              // 0..3  (rows of 64)
    const int wn  = wid & 1;               // 0..1  (cols of 64)
    const int m0  = blockIdx.y << 8;       // 256-row tiles
    const int n0  = blockIdx.x << 7;       // 128-col tiles
    const int z   = blockIdx.z;
    const __nv_bfloat16* __restrict__ Ah = bt.Ah[z];
    const __nv_bfloat16* __restrict__ Al = bt.Al[z];
    const __nv_bfloat16* __restrict__ Bh = bt.Bh[z];
    const __nv_bfloat16* __restrict__ Bl = bt.Bl[z];
    float* __restrict__ C = bt.C[z];

    const uint32_t sbase = smem_u32(dsm);
    const int cr = tid >> 2, cc = tid & 3;      // copy row/16B-col

    auto issue = [&](int kc, int st) {
        const uint32_t sb = sbase + st * STAGE;
        const size_t ka = (size_t)kc * 32 + cc * 8;
        // A: 256 rows (hi+lo)
#pragma unroll
        for (int j = 0; j < 4; ++j) {
            int r = cr + j * 64;
            uint32_t so = sb + r * 80 + cc * 16;
            cp16(so,         Ah + (size_t)(m0 + r) * K + ka);
            cp16(so + 20480, Al + (size_t)(m0 + r) * K + ka);
        }
        // B: 128 rows (hi+lo)
#pragma unroll
        for (int j = 0; j < 2; ++j) {
            int r = cr + j * 64;
            uint32_t so = sb + 40960 + r * 80 + cc * 16;
            cp16(so,         Bh + (size_t)(n0 + r) * K + ka);
            cp16(so + 10240, Bl + (size_t)(n0 + r) * K + ka);
        }
    };

    wmma::fragment<wmma::accumulator, 16, 16, 16, float> acc[4][4];
#pragma unroll
    for (int i = 0; i < 4; ++i)
#pragma unroll
        for (int j = 0; j < 4; ++j) wmma::fill_fragment(acc[i][j], 0.f);

    const int NC = K >> 5;
    issue(0, 0);
    asm volatile("cp.async.commit_group;");
    issue(1, 1);
    asm volatile("cp.async.commit_group;");

    int st = 0;
    for (int c = 0; c < NC; ++c) {
        asm volatile("cp.async.wait_group 1;");
        __syncthreads();
        if (c + 2 < NC) {
            int st2 = st + 2; if (st2 >= 3) st2 -= 3;
            issue(c + 2, st2);
        }
        asm volatile("cp.async.commit_group;");

        const char* bp = dsm + st * STAGE;
        const __nv_bfloat16* ah = (const __nv_bfloat16*)(bp);
        const __nv_bfloat16* al = (const __nv_bfloat16*)(bp + 20480);
        const __nv_bfloat16* bh = (const __nv_bfloat16*)(bp + 40960);
        const __nv_bfloat16* bl = (const __nv_bfloat16*)(bp + 51200);

#pragma unroll
        for (int kk = 0; kk < 2; ++kk) {
            wmma::fragment<wmma::matrix_b, 16, 16, 16, __nv_bfloat16, wmma::col_major> bfh[4], bfl[4];
#pragma unroll
            for (int ni = 0; ni < 4; ++ni) {
                wmma::load_matrix_sync(bfh[ni], bh + (wn * 64 + ni * 16) * 40 + kk * 16, 40);
                wmma::load_matrix_sync(bfl[ni], bl + (wn * 64 + ni * 16) * 40 + kk * 16, 40);
            }
#pragma unroll
            for (int mi = 0; mi < 4; ++mi) {
                wmma::fragment<wmma::matrix_a, 16, 16, 16, __nv_bfloat16, wmma::row_major> afh, afl;
                wmma::load_matrix_sync(afh, ah + (wm * 64 + mi * 16) * 40 + kk * 16, 40);
                wmma::load_matrix_sync(afl, al + (wm * 64 + mi * 16) * 40 + kk * 16, 40);
#pragma unroll
                for (int ni = 0; ni < 4; ++ni) {
                    wmma::mma_sync(acc[mi][ni], afh, bfl[ni], acc[mi][ni]);
                    wmma::mma_sync(acc[mi][ni], afl, bfh[ni], acc[mi][ni]);
                    wmma::mma_sync(acc[mi][ni], afh, bfh[ni], acc[mi][ni]);
                }
            }
        }
        if (++st >= 3) st -= 3;
    }

    const int epi_mode = bt.epi[z];
    if (epi_mode == 0) {
#pragma unroll
        for (int mi = 0; mi < 4; ++mi)
#pragma unroll
            for (int ni = 0; ni < 4; ++ni)
                wmma::store_matrix_sync(C + (size_t)(m0 + wm * 64 + mi * 16) * N + n0 + wn * 64 + ni * 16,
                                        acc[mi][ni], N, wmma::mem_row_major);
        return;
    }

    // stage acc tile (256 x 128) to smem
    __syncthreads();
    float* ep = (float*)dsm;
#pragma unroll
    for (int mi = 0; mi < 4; ++mi)
#pragma unroll
        for (int ni = 0; ni < 4; ++ni)
            wmma::store_matrix_sync(ep + (wm * 64 + mi * 16) * EPS + wn * 64 + ni * 16,
                                    acc[mi][ni], EPS, wmma::mem_row_major);
    __syncthreads();

    if (epi_mode == 1) {
        // per-row L2 norm (tile N-width 128 == one head)
        {
            float ss = 0.f;
#pragma unroll 8
            for (int i = 0; i < 128; ++i) {
                float v = ep[tid * EPS + i];
                ss = fmaf(v, v, ss);
            }
            sc[tid] = 1.f / fmaxf(sqrtf(ss), 1e-12f);
        }
        __syncthreads();
        __nv_bfloat16* Hb = bt.eh[z];
        __nv_bfloat16* Lb = bt.el[z];
        const long long es = bt.estride[z], ec = bt.ecol[z];
#pragma unroll 4
        for (int i = 0; i < 32; ++i) {
            int r = wid * 32 + i;
            size_t row = m0 + r;
            float4 v = *(float4*)(ep + r * EPS + lane * 4);
            split4_store(v, Hb + row * es + ec + n0, Lb + row * es + ec + n0, lane * 4);
            const float s = sc[r];
            v.x *= s; v.y *= s; v.z *= s; v.w *= s;
            *(float4*)(C + row * N + n0 + lane * 4) = v;
        }
    } else if (epi_mode == 2) {
        __nv_bfloat16* Hb = bt.eh[z];
        __nv_bfloat16* Lb = bt.el[z];
        const long long es = bt.estride[z];
#pragma unroll 4
        for (int i = 0; i < 32; ++i) {
            int r = wid * 32 + i;
            size_t row = m0 + r;
            float4 v = *(float4*)(ep + r * EPS + lane * 4);
            v.x = v.x * sigmoidf_(v.x);
            v.y = v.y * sigmoidf_(v.y);
            v.z = v.z * sigmoidf_(v.z);
            v.w = v.w * sigmoidf_(v.w);
            split4_store(v, Hb + row * es + n0, Lb + row * es + n0, lane * 4);
        }
    } else {
        // EPI 3: dynamic conv. Tile = kern[rows][32 d x 4 w]; d = n0/4 + lane.
        const int d = (n0 >> 2) + lane;
        const float4 bb = *(const float4*)(bt.bias + n0 + lane * 4);
        const float* vcol = bt.vsrc + d;
        const int rbase = m0 + wid * 32;
        float vw0, vw1, vw2, vw3;
        {
            int tl = rbase & 2047;
            vw0 = (tl >= 3) ? vcol[(size_t)(rbase - 3) * 2048] : 0.f;
            vw1 = (tl >= 2) ? vcol[(size_t)(rbase - 2) * 2048] : 0.f;
            vw2 = (tl >= 1) ? vcol[(size_t)(rbase - 1) * 2048] : 0.f;
        }
#pragma unroll
        for (int i = 0; i < 32; ++i) {
            const int row = rbase + i;
            const int tl = row & 2047;
            vw3 = vcol[(size_t)row * 2048];
            float4 kf = *(const float4*)(ep + (wid * 32 + i) * EPS + lane * 4);
            kf.x += bb.x; kf.y += bb.y; kf.z += bb.z; kf.w += bb.w;
            float a0 = (tl >= 3) ? vw0 : 0.f;
            float a1 = (tl >= 2) ? vw1 : 0.f;
            float a2 = (tl >= 1) ? vw2 : 0.f;
            float acc2 = kf.x * a0 + kf.y * a1 + kf.z * a2 + kf.w * vw3;
            C[(size_t)row * 2048 + d] = acc2 * sigmoidf_(acc2);
            vw0 = vw1; vw1 = vw2; vw2 = vw3;
        }
    }
}

// ---------------------------------------------------------------------------
// beta / decay
// ---------------------------------------------------------------------------
__global__ void __launch_bounds__(256) betag_kernel(
    const float* __restrict__ x, const float* __restrict__ Wb, const float* __restrict__ Wa,
    const float* __restrict__ dtb, const float* __restrict__ Alog,
    float* __restrict__ beta, float* __restrict__ decay)
{
    __shared__ float xs[16][128];
    __shared__ float wbs[128 * 17];
    __shared__ float was[128 * 17];
    const int tid = threadIdx.x;
    const int myrow = tid >> 4, mycol = tid & 15;
    const int r0 = blockIdx.x * 16;
    float pb = 0.f, pa = 0.f;
    for (int ch = 0; ch < 16; ++ch) {
        __syncthreads();
#pragma unroll
        for (int j = 0; j < 8; ++j) {
            int lin = tid + j * 256;
            int rr = lin >> 7, cccol = lin & 127;
            xs[rr][cccol] = x[(size_t)(r0 + rr) * 2048 + ch * 128 + cccol];
            int wi = lin >> 4, wc = lin & 15;
            wbs[wi * 17 + wc] = Wb[(size_t)ch * 2048 + lin];
            was[wi * 17 + wc] = Wa[(size_t)ch * 2048 + lin];
        }
        __syncthreads();
#pragma unroll 8
        for (int i = 0; i < 128; ++i) {
            float xv = xs[myrow][i];
            pb = fmaf(xv, wbs[i * 17 + mycol], pb);
            pa = fmaf(xv, was[i * 17 + mycol], pa);
        }
    }
    int row = r0 + myrow;
    beta[row * 16 + mycol] = 1.f / (1.f + expf(-pb));
    float z = pa + dtb[mycol];
    float sp = (z > 20.f) ? z : log1pf(expf(z));
    decay[row * 16 + mycol] = expf(-expf(Alog[mycol]) * sp);
}

// ---------------------------------------------------------------------------
// Gated delta rule recurrence, time-tiled with cp.async
// ---------------------------------------------------------------------------
#define TT 16
__global__ void __launch_bounds__(256, 1) recur_kernel(
    const float* __restrict__ qn, const float* __restrict__ kn,
    const float* __restrict__ v, const float* __restrict__ decay,
    const float* __restrict__ beta, float* __restrict__ o)
{
    __shared__ float qt[2][TT * 128];
    __shared__ float kt[2][TT * 128];
    __shared__ float vt[2][TT * 32];
    __shared__ float gt[2][TT];
    __shared__ float bt[2][TT];
    __shared__ float ob[TT * 32];

    const int bx = blockIdx.x;
    const int bh = bx >> 2;
    const int dvblk = bx & 3;
    const int b = bh >> 4;
    const int h = bh & 15;
    const int tid = threadIdx.x;
    const int dkg = tid & 7;
    const int dvi = tid >> 3;

    const size_t row0 = (size_t)b * 2048;
    const float* qrow = qn + row0 * 2048 + h * 128;
    const float* krow = kn + row0 * 2048 + h * 128;
    const float* vrow = v + row0 * 2048 + h * 128 + dvblk * 32;
    const float* grow = decay + row0 * 16 + h;
    const float* brow = beta + row0 * 16 + h;
    float* obase = o + row0 * 2048 + h * 128 + dvblk * 32;

    float S[16];
#pragma unroll
    for (int i = 0; i < 16; ++i) S[i] = 0.f;

    auto issue_tile = [&](int tt, int buf) {
        const int t0 = tt * TT;
#pragma unroll
        for (int j = 0; j < 2; ++j) {
            int c = tid + j * 256;
            int stp = c >> 5, of = c & 31;
            cp16(smem_u32(&qt[buf][stp * 128 + of * 4]),
                 qrow + (size_t)(t0 + stp) * 2048 + of * 4);
            cp16(smem_u32(&kt[buf][stp * 128 + of * 4]),
                 krow + (size_t)(t0 + stp) * 2048 + of * 4);
        }
        if (tid < 128) {
            int stp = tid >> 3, of = tid & 7;
            cp16(smem_u32(&vt[buf][stp * 32 + of * 4]),
                 vrow + (size_t)(t0 + stp) * 2048 + of * 4);
        } else if (tid < 144) {
            int i = tid - 128;
            cp4(smem_u32(&gt[buf][i]), grow + (size_t)(t0 + i) * 16);
        } else if (tid < 160) {
            int i = tid - 144;
            cp4(smem_u32(&bt[buf][i]), brow + (size_t)(t0 + i) * 16);
        }
    };

    issue_tile(0, 0);
    asm volatile("cp.async.commit_group;");

    const int NT = 2048 / TT;
    for (int tt = 0; tt < NT; ++tt) {
        asm volatile("cp.async.wait_group 0;");
        __syncthreads();
        const int buf = tt & 1;
        if (tt + 1 < NT) issue_tile(tt + 1, buf ^ 1);
        asm volatile("cp.async.commit_group;");

#pragma unroll 4
        for (int stp = 0; stp < TT; ++stp) {
            float qv[16], kv[16];
#pragma unroll
            for (int j = 0; j < 4; ++j) {
                float4 a = *(const float4*)&qt[buf][stp * 128 + (dkg + 8 * j) * 4];
                qv[j * 4 + 0] = a.x; qv[j * 4 + 1] = a.y; qv[j * 4 + 2] = a.z; qv[j * 4 + 3] = a.w;
                float4 c = *(const float4*)&kt[buf][stp * 128 + (dkg + 8 * j) * 4];
                kv[j * 4 + 0] = c.x; kv[j * 4 + 1] = c.y; kv[j * 4 + 2] = c.z; kv[j * 4 + 3] = c.w;
            }
            float o0 = 0.f, o1 = 0.f, s0 = 0.f, s1 = 0.f;
#pragma unroll
            for (int i = 0; i < 16; i += 2) {
                o0 = fmaf(S[i],     qv[i],     o0);
                o1 = fmaf(S[i + 1], qv[i + 1], o1);
                s0 = fmaf(S[i],     kv[i],     s0);
                s1 = fmaf(S[i + 1], kv[i + 1], s1);
            }
            float ot = o0 + o1, sk = s0 + s1;
#pragma unroll
            for (int m = 4; m >= 1; m >>= 1) {
                ot += __shfl_xor_sync(0xffffffffu, ot, m);
                sk += __shfl_xor_sync(0xffffffffu, sk, m);
            }
            const float gv = gt[buf][stp];
            const float bv = bt[buf][stp];
            const float vv = vt[buf][stp * 32 + dvi];
            const float ccc = bv * (vv - sk);
#pragma unroll
            for (int i = 0; i < 16; ++i)
                S[i] = fmaf(ccc, kv[i], S[i] * gv);
            if (dkg == 0) ob[stp * 32 + dvi] = ot;
        }
        __syncthreads();
        if (tid < 128) {
            int stp = tid >> 3, of = tid & 7;
            float4 val = *(const float4*)&ob[stp * 32 + of * 4];
            *(float4*)(obase + (size_t)(tt * TT + stp) * 2048 + of * 4) = val;
        }
    }
}

// ---------------------------------------------------------------------------
// Gated RMSNorm -> split bf16 directly
// ---------------------------------------------------------------------------
__global__ void __launch_bounds__(256) rmsgate_kernel(
    const float* __restrict__ o, const float* __restrict__ xg,
    const float* __restrict__ nw,
    __nv_bfloat16* __restrict__ H, __nv_bfloat16* __restrict__ L)
{
    int u = blockIdx.x * 8 + (threadIdx.x >> 5);
    int lane = threadIdx.x & 31;
    size_t base = (size_t)u * 128 + lane * 4;
    float4 a = *(const float4*)(o + base);
    float ss = a.x * a.x + a.y * a.y + a.z * a.z + a.w * a.w;
#pragma unroll
    for (int m = 16; m >= 1; m >>= 1) ss += __shfl_xor_sync(0xffffffffu, ss, m);
    float r = rsqrtf(ss * (1.f / 128.f) + 1e-6f);
    float4 g = *(const float4*)(xg + base);
    float4 w = *(const float4*)(nw + lane * 4);
    float4 out;
    out.x = a.x * r * w.x * (g.x * sigmoidf_(g.x));
    out.y = a.y * r * w.y * (g.y * sigmoidf_(g.y));
    out.z = a.z * r * w.z * (g.z * sigmoidf_(g.z));
    out.w = a.w * r * w.w * (g.w * sigmoidf_(g.w));
    split4_store(out, H, L, base);
}

// ---------------------------------------------------------------------------
extern "C" void kernel_launch(void* const* d_in, const int* in_sizes, int n_in,
                              void* d_out, int out_size)
{
    const float* x    = (const float*)d_in[0];
    const float* Wq   = (const float*)d_in[1];
    const float* Wk   = (const float*)d_in[2];
    const float* Wv   = (const float*)d_in[3];
    const float* Wb   = (const float*)d_in[4];
    const float* Wa   = (const float*)d_in[5];
    const float* dtb  = (const float*)d_in[6];
    const float* Alog = (const float*)d_in[7];
    const float* W1   = (const float*)d_in[8];
    const float* W2   = (const float*)d_in[9];
    const float* b2   = (const float*)d_in[10];
    const float* nw   = (const float*)d_in[11];
    const float* Wg   = (const float*)d_in[12];
    const float* Wo   = (const float*)d_in[13];
    float* out = (float*)d_out;

    float *q, *k, *v, *v2, *o, *xg, *beta, *decay;
    __nv_bfloat16 *wth, *wtl, *p0h, *p0l, *pqh, *pql;
    cudaGetSymbolAddress((void**)&q,     g_q);
    cudaGetSymbolAddress((void**)&k,     g_k);
    cudaGetSymbolAddress((void**)&v,     g_v);
    cudaGetSymbolAddress((void**)&v2,    g_v2);
    cudaGetSymbolAddress((void**)&o,     g_o);
    cudaGetSymbolAddress((void**)&xg,    g_xg);
    cudaGetSymbolAddress((void**)&beta,  g_beta);
    cudaGetSymbolAddress((void**)&decay, g_decay);
    cudaGetSymbolAddress((void**)&wth,   g_wth);
    cudaGetSymbolAddress((void**)&wtl,   g_wtl);
    cudaGetSymbolAddress((void**)&p0h,   g_p0h);
    cudaGetSymbolAddress((void**)&p0l,   g_p0l);
    cudaGetSymbolAddress((void**)&pqh,   g_pqh);
    cudaGetSymbolAddress((void**)&pql,   g_pql);

    const int SMEM = 3 * STAGE;   // 184320
    cudaFuncSetAttribute(gemm_cp, cudaFuncAttributeMaxDynamicSharedMemorySize, SMEM);

    // 0) weight prep
    {
        PrepBatch pb{};
        pb.W[0] = Wq;  pb.off[0] = OFF_Q;
        pb.W[1] = Wk;  pb.off[1] = OFF_K;
        pb.W[2] = Wv;  pb.off[2] = OFF_V;
        pb.W[3] = Wg;  pb.off[3] = OFF_G;
        pb.W[4] = Wo;  pb.off[4] = OFF_WO;
        prep_kernel<<<dim3(64, 64, 5), 256>>>(pb, wth, wtl, 2048, 2048);
        PrepBatch p1{};
        p1.W[0] = W1;  p1.off[0] = OFF_W1;
        prep_kernel<<<dim3(64, 128, 1), 256>>>(p1, wth, wtl, 2048, 4096);
        PrepBatch p2{};
        p2.W[0] = W2;  p2.off[0] = OFF_W2;
        prep_kernel<<<dim3(256, 64, 1), 256>>>(p2, wth, wtl, 8192, 2048);
    }
    // 0b) split x
    split_kernel<<<8192, 256>>>(x, p0h, p0l);
    // 1) fused projections: q,k (EPI1), v,xg (EPI0)   grid (N/128, M/256, 4)
    {
        GB bt{};
        for (int z = 0; z < 4; ++z) { bt.Ah[z] = p0h; bt.Al[z] = p0l; }
        bt.Bh[0] = wth + OFF_Q; bt.Bh[1] = wth + OFF_K; bt.Bh[2] = wth + OFF_V; bt.Bh[3] = wth + OFF_G;
        bt.Bl[0] = wtl + OFF_Q; bt.Bl[1] = wtl + OFF_K; bt.Bl[2] = wtl + OFF_V; bt.Bl[3] = wtl + OFF_G;
        bt.C[0] = q; bt.C[1] = k; bt.C[2] = v; bt.C[3] = xg;
        bt.epi[0] = 1; bt.epi[1] = 1; bt.epi[2] = 0; bt.epi[3] = 0;
        bt.eh[0] = pqh; bt.el[0] = pql; bt.estride[0] = 4096; bt.ecol[0] = 0;
        bt.eh[1] = pqh; bt.el[1] = pql; bt.estride[1] = 4096; bt.ecol[1] = 2048;
        gemm_cp<<<dim3(16, 16, 4), 256, SMEM>>>(bt, 4096, 2048, 2048);
    }
    betag_kernel<<<256, 256>>>(x, Wb, Wa, dtb, Alog, beta, decay);
    // 2) generator layer 1 (K=4096), EPI2: silu + split
    {
        GB bt{};
        bt.Ah[0] = pqh; bt.Al[0] = pql;
        bt.Bh[0] = wth + OFF_W1; bt.Bl[0] = wtl + OFF_W1;
        bt.C[0] = nullptr;
        bt.epi[0] = 2;
        bt.eh[0] = p0h; bt.el[0] = p0l; bt.estride[0] = 2048; bt.ecol[0] = 0;
        gemm_cp<<<dim3(16, 16, 1), 256, SMEM>>>(bt, 4096, 2048, 4096);
    }
    // 3) generator layer 2 + bias + dynamic conv + SiLU -> v2 (EPI3)
    {
        GB bt{};
        bt.Ah[0] = p0h; bt.Al[0] = p0l;
        bt.Bh[0] = wth + OFF_W2; bt.Bl[0] = wtl + OFF_W2;
        bt.C[0] = v2;
        bt.epi[0] = 3;
        bt.vsrc = v; bt.bias = b2;
        gemm_cp<<<dim3(64, 16, 1), 256, SMEM>>>(bt, 4096, 8192, 2048);
    }
    // 4) recurrence
    recur_kernel<<<128, 256>>>(q, k, v2, decay, beta, o);
    // 5) gated RMSNorm -> og split
    rmsgate_kernel<<<8192, 256>>>(o, xg, nw, p0h, p0l);
    // 6) output projection
    {
        GB bt{};
        bt.Ah[0] = p0h; bt.Al[0] = p0l;
        bt.Bh[0] = wth + OFF_WO; bt.Bl[0] = wtl + OFF_WO;
        bt.C[0] = out;
        bt.epi[0] = 0;
        gemm_cp<<<dim3(16, 16, 1), 256, SMEM>>>(bt, 4096, 2048, 2048);
    }
}

// round 9
// speedup vs baseline: 1.0316x; 1.0316x over previous
#include <cuda_runtime.h>
#include <cuda_bf16.h>
#include <mma.h>
#include <cstdint>

using namespace nvcuda;

// ---------------------------------------------------------------------------
// Dims (fixed): B=2, T=2048, HID=2048, H=16, DK=DV=128, W=4; rows = B*T = 4096
// Toolchain lowers to compute_103 PTX (no tcgen05). Stay sm_80-portable.
// GEMM: 128x128 CTA, 2 CTAs/SM, 2-stage cp.async (R7 config — best measured).
// ---------------------------------------------------------------------------

__device__ float g_q   [4096ll * 2048];   // NORMALIZED q
__device__ float g_k   [4096ll * 2048];   // NORMALIZED k
__device__ float g_v   [4096ll * 2048];
__device__ float g_v2  [4096ll * 2048];   // silu(conv(v))
__device__ float g_o   [4096ll * 2048];
__device__ float g_xg  [4096ll * 2048];
__device__ float g_beta [4096 * 16];
__device__ float g_decay[4096 * 16];

#define MELEM 4194304ll
#define OFF_Q   (0ll)
#define OFF_K   (1ll * MELEM)
#define OFF_V   (2ll * MELEM)
#define OFF_G   (3ll * MELEM)
#define OFF_W1  (4ll * MELEM)
#define OFF_WO  (6ll * MELEM)
#define OFF_W2  (7ll * MELEM)
__device__ __nv_bfloat16 g_wth[11ll * MELEM];
__device__ __nv_bfloat16 g_wtl[11ll * MELEM];

__device__ __nv_bfloat16 g_p0h[4096ll * 2048];
__device__ __nv_bfloat16 g_p0l[4096ll * 2048];
__device__ __nv_bfloat16 g_pqh[4096ll * 4096];
__device__ __nv_bfloat16 g_pql[4096ll * 4096];

__device__ __forceinline__ float sigmoidf_(float x) { return 1.f / (1.f + expf(-x)); }

__device__ __forceinline__ uint32_t smem_u32(const void* p) {
    uint32_t a;
    asm("{ .reg .u64 t; cvta.to.shared.u64 t, %1; cvt.u32.u64 %0, t; }" : "=r"(a) : "l"(p));
    return a;
}
__device__ __forceinline__ void cp16(uint32_t so, const void* g) {
    asm volatile("cp.async.cg.shared.global [%0], [%1], 16;" :: "r"(so), "l"(g));
}
__device__ __forceinline__ void cp4(uint32_t so, const void* g) {
    asm volatile("cp.async.ca.shared.global [%0], [%1], 4;" :: "r"(so), "l"(g));
}

__device__ __forceinline__ void split2(float x, float y, uint32_t& hu, uint32_t& lu) {
    __nv_bfloat16 hx = __float2bfloat16_rn(x), hy = __float2bfloat16_rn(y);
    __nv_bfloat16 lx = __float2bfloat16_rn(x - __bfloat162float(hx));
    __nv_bfloat16 ly = __float2bfloat16_rn(y - __bfloat162float(hy));
    __nv_bfloat162 h(hx, hy), l(lx, ly);
    hu = *(uint32_t*)&h;
    lu = *(uint32_t*)&l;
}
__device__ __forceinline__ void split4_store(
    float4 v, __nv_bfloat16* __restrict__ h, __nv_bfloat16* __restrict__ l, size_t i)
{
    uint2 hu, lu;
    split2(v.x, v.y, hu.x, lu.x);
    split2(v.z, v.w, hu.y, lu.y);
    *(uint2*)(h + i) = hu;
    *(uint2*)(l + i) = lu;
}

// ---------------------------------------------------------------------------
// Weight prep
// ---------------------------------------------------------------------------
struct PrepBatch { const float* W[5]; long long off[5]; };

__global__ void __launch_bounds__(256) prep_kernel(
    PrepBatch pb, __nv_bfloat16* __restrict__ Th, __nv_bfloat16* __restrict__ Tl,
    int N, int Kd)
{
    __shared__ float s[32][33];
    const float* W = pb.W[blockIdx.z];
    const long long base = pb.off[blockIdx.z];
    const int n0 = blockIdx.x * 32, k0 = blockIdx.y * 32;
    const int tid = threadIdx.x;
#pragma unroll
    for (int j = 0; j < 4; ++j) {
        int lin = tid + j * 256;
        int kk = lin >> 5, nn = lin & 31;
        s[kk][nn] = W[(size_t)(k0 + kk) * N + n0 + nn];
    }
    __syncthreads();
#pragma unroll
    for (int j = 0; j < 4; ++j) {
        int lin = tid + j * 256;
        int nn = lin >> 5, kk = lin & 31;
        float v = s[kk][nn];
        __nv_bfloat16 h = __float2bfloat16_rn(v);
        __nv_bfloat16 l = __float2bfloat16_rn(v - __bfloat162float(h));
        size_t o = (size_t)base + (size_t)(n0 + nn) * Kd + k0 + kk;
        Th[o] = h;
        Tl[o] = l;
    }
}

__global__ void __launch_bounds__(256) split_kernel(
    const float* __restrict__ s, __nv_bfloat16* __restrict__ h, __nv_bfloat16* __restrict__ l)
{
    size_t i = ((size_t)blockIdx.x * 256 + threadIdx.x) * 4;
    split4_store(*(const float4*)(s + i), h, l, i);
}

// ---------------------------------------------------------------------------
// Split-bf16 HMMA GEMM, cp.async pipeline, fused epilogues (R7 config).
// ---------------------------------------------------------------------------
struct GB {
    const __nv_bfloat16* Ah[4]; const __nv_bfloat16* Al[4];
    const __nv_bfloat16* Bh[4]; const __nv_bfloat16* Bl[4];
    float* C[4];
    int epi[4];
    __nv_bfloat16* eh[4]; __nv_bfloat16* el[4];
    long long estride[4]; long long ecol[4];
    const float* vsrc; const float* bias;
};

#define EPS 140

__global__ void __launch_bounds__(256, 2) gemm_cp(
    GB bt, int M, int N, int K)
{
    extern __shared__ __align__(16) char dsm[];
    __shared__ float sc[128];
    const int tid = threadIdx.x;
    const int wid = tid >> 5;
    const int wm  = wid >> 2;
    const int wn  = wid & 3;
    const int m0  = blockIdx.y << 7;
    const int n0  = blockIdx.x << 7;
    const int z   = blockIdx.z;
    const __nv_bfloat16* __restrict__ Ah = bt.Ah[z];
    const __nv_bfloat16* __restrict__ Al = bt.Al[z];
    const __nv_bfloat16* __restrict__ Bh = bt.Bh[z];
    const __nv_bfloat16* __restrict__ Bl = bt.Bl[z];
    float* __restrict__ C = bt.C[z];

    const uint32_t sbase = smem_u32(dsm);
    const int r0 = tid >> 2, c16 = tid & 3;
    const int r1 = r0 + 64;

    auto issue = [&](int s, int kc) {
        const uint32_t sb = sbase + s * 40960;
        const size_t ka = (size_t)kc * 32 + c16 * 8;
        {
            uint32_t so = sb + r0 * 80 + c16 * 16;
            cp16(so,         Ah + (size_t)(m0 + r0) * K + ka);
            cp16(so + 10240, Al + (size_t)(m0 + r0) * K + ka);
            cp16(so + 20480, Bh + (size_t)(n0 + r0) * K + ka);
            cp16(so + 30720, Bl + (size_t)(n0 + r0) * K + ka);
        }
        {
            uint32_t so = sb + r1 * 80 + c16 * 16;
            cp16(so,         Ah + (size_t)(m0 + r1) * K + ka);
            cp16(so + 10240, Al + (size_t)(m0 + r1) * K + ka);
            cp16(so + 20480, Bh + (size_t)(n0 + r1) * K + ka);
            cp16(so + 30720, Bl + (size_t)(n0 + r1) * K + ka);
        }
    };

    wmma::fragment<wmma::accumulator, 16, 16, 16, float> acc[4][2];
#pragma unroll
    for (int i = 0; i < 4; ++i)
#pragma unroll
        for (int j = 0; j < 2; ++j) wmma::fill_fragment(acc[i][j], 0.f);

    issue(0, 0);
    asm volatile("cp.async.commit_group;");

    const int NC = K >> 5;
    for (int c = 0; c < NC; ++c) {
        const int s = c & 1;
        if (c + 1 < NC) issue(s ^ 1, c + 1);
        asm volatile("cp.async.commit_group;");
        asm volatile("cp.async.wait_group 1;");
        __syncthreads();

        const __nv_bfloat16* ah = (const __nv_bfloat16*)(dsm + s * 40960);
        const __nv_bfloat16* al = (const __nv_bfloat16*)(dsm + s * 40960 + 10240);
        const __nv_bfloat16* bh = (const __nv_bfloat16*)(dsm + s * 40960 + 20480);
        const __nv_bfloat16* bl = (const __nv_bfloat16*)(dsm + s * 40960 + 30720);

#pragma unroll
        for (int kk = 0; kk < 2; ++kk) {
            wmma::fragment<wmma::matrix_b, 16, 16, 16, __nv_bfloat16, wmma::col_major> bfh[2], bfl[2];
#pragma unroll
            for (int ni = 0; ni < 2; ++ni) {
                wmma::load_matrix_sync(bfh[ni], bh + (wn * 32 + ni * 16) * 40 + kk * 16, 40);
                wmma::load_matrix_sync(bfl[ni], bl + (wn * 32 + ni * 16) * 40 + kk * 16, 40);
            }
#pragma unroll
            for (int mi = 0; mi < 4; ++mi) {
                wmma::fragment<wmma::matrix_a, 16, 16, 16, __nv_bfloat16, wmma::row_major> afh, afl;
                wmma::load_matrix_sync(afh, ah + (wm * 64 + mi * 16) * 40 + kk * 16, 40);
                wmma::load_matrix_sync(afl, al + (wm * 64 + mi * 16) * 40 + kk * 16, 40);
#pragma unroll
                for (int ni = 0; ni < 2; ++ni) {
                    wmma::mma_sync(acc[mi][ni], afh, bfl[ni], acc[mi][ni]);
                    wmma::mma_sync(acc[mi][ni], afl, bfh[ni], acc[mi][ni]);
                    wmma::mma_sync(acc[mi][ni], afh, bfh[ni], acc[mi][ni]);
                }
            }
        }
        __syncthreads();
    }

    const int epi_mode = bt.epi[z];
    if (epi_mode == 0) {
#pragma unroll
        for (int mi = 0; mi < 4; ++mi)
#pragma unroll
            for (int ni = 0; ni < 2; ++ni)
                wmma::store_matrix_sync(C + (size_t)(m0 + wm * 64 + mi * 16) * N + n0 + wn * 32 + ni * 16,
                                        acc[mi][ni], N, wmma::mem_row_major);
        return;
    }

    float* ep = (float*)dsm;
#pragma unroll
    for (int mi = 0; mi < 4; ++mi)
#pragma unroll
        for (int ni = 0; ni < 2; ++ni)
            wmma::store_matrix_sync(ep + (wm * 64 + mi * 16) * EPS + wn * 32 + ni * 16,
                                    acc[mi][ni], EPS, wmma::mem_row_major);
    __syncthreads();

    if (epi_mode == 1) {
        if (tid < 128) {
            float ss = 0.f;
#pragma unroll 8
            for (int i = 0; i < 128; ++i) {
                float v = ep[tid * EPS + i];
                ss = fmaf(v, v, ss);
            }
            sc[tid] = 1.f / fmaxf(sqrtf(ss), 1e-12f);
        }
        __syncthreads();
        const int r = tid >> 1, c0 = (tid & 1) * 64;
        const float s = sc[r];
        const size_t row = m0 + r;
        float* Cp = C + row * N + n0 + c0;
        __nv_bfloat16* H = bt.eh[z] + row * bt.estride[z] + bt.ecol[z] + n0 + c0;
        __nv_bfloat16* L = bt.el[z] + row * bt.estride[z] + bt.ecol[z] + n0 + c0;
#pragma unroll
        for (int j = 0; j < 16; ++j) {
            float4 v = *(float4*)(ep + r * EPS + c0 + j * 4);
            split4_store(v, H, L, j * 4);
            v.x *= s; v.y *= s; v.z *= s; v.w *= s;
            *(float4*)(Cp + j * 4) = v;
        }
    } else if (epi_mode == 2) {
        const int r = tid >> 1, c0 = (tid & 1) * 64;
        const size_t row = m0 + r;
        __nv_bfloat16* H = bt.eh[z] + row * bt.estride[z] + n0 + c0;
        __nv_bfloat16* L = bt.el[z] + row * bt.estride[z] + n0 + c0;
#pragma unroll
        for (int j = 0; j < 16; ++j) {
            float4 v = *(float4*)(ep + r * EPS + c0 + j * 4);
            v.x = v.x * sigmoidf_(v.x);
            v.y = v.y * sigmoidf_(v.y);
            v.z = v.z * sigmoidf_(v.z);
            v.w = v.w * sigmoidf_(v.w);
            split4_store(v, H, L, j * 4);
        }
    } else {
        const int dd = tid & 31;
        const int rb = (tid >> 5) * 16;
        const int d = (n0 >> 2) + dd;
        const float4 bb = *(const float4*)(bt.bias + n0 + dd * 4);
        const float* vcol = bt.vsrc + d;
        float vw0, vw1, vw2, vw3;
        {
            int row0 = m0 + rb;
            int tl = row0 & 2047;
            vw0 = (tl >= 3) ? vcol[(size_t)(row0 - 3) * 2048] : 0.f;
            vw1 = (tl >= 2) ? vcol[(size_t)(row0 - 2) * 2048] : 0.f;
            vw2 = (tl >= 1) ? vcol[(size_t)(row0 - 1) * 2048] : 0.f;
        }
#pragma unroll
        for (int i = 0; i < 16; ++i) {
            const int row = m0 + rb + i;
            const int tl = row & 2047;
            vw3 = vcol[(size_t)row * 2048];
            float4 kf = *(const float4*)(ep + (rb + i) * EPS + dd * 4);
            kf.x += bb.x; kf.y += bb.y; kf.z += bb.z; kf.w += bb.w;
            float a0 = (tl >= 3) ? vw0 : 0.f;
            float a1 = (tl >= 2) ? vw1 : 0.f;
            float a2 = (tl >= 1) ? vw2 : 0.f;
            float acc2 = kf.x * a0 + kf.y * a1 + kf.z * a2 + kf.w * vw3;
            C[(size_t)row * 2048 + d] = acc2 * sigmoidf_(acc2);
            vw0 = vw1; vw1 = vw2; vw2 = vw3;
        }
    }
}

// ---------------------------------------------------------------------------
// beta / decay
// ---------------------------------------------------------------------------
__global__ void __launch_bounds__(256) betag_kernel(
    const float* __restrict__ x, const float* __restrict__ Wb, const float* __restrict__ Wa,
    const float* __restrict__ dtb, const float* __restrict__ Alog,
    float* __restrict__ beta, float* __restrict__ decay)
{
    __shared__ float xs[16][128];
    __shared__ float wbs[128 * 17];
    __shared__ float was[128 * 17];
    const int tid = threadIdx.x;
    const int myrow = tid >> 4, mycol = tid & 15;
    const int r0 = blockIdx.x * 16;
    float pb = 0.f, pa = 0.f;
    for (int ch = 0; ch < 16; ++ch) {
        __syncthreads();
#pragma unroll
        for (int j = 0; j < 8; ++j) {
            int lin = tid + j * 256;
            int rr = lin >> 7, cc = lin & 127;
            xs[rr][cc] = x[(size_t)(r0 + rr) * 2048 + ch * 128 + cc];
            int wi = lin >> 4, wc = lin & 15;
            wbs[wi * 17 + wc] = Wb[(size_t)ch * 2048 + lin];
            was[wi * 17 + wc] = Wa[(size_t)ch * 2048 + lin];
        }
        __syncthreads();
#pragma unroll 8
        for (int i = 0; i < 128; ++i) {
            float xv = xs[myrow][i];
            pb = fmaf(xv, wbs[i * 17 + mycol], pb);
            pa = fmaf(xv, was[i * 17 + mycol], pa);
        }
    }
    int row = r0 + myrow;
    beta[row * 16 + mycol] = 1.f / (1.f + expf(-pb));
    float z = pa + dtb[mycol];
    float sp = (z > 20.f) ? z : log1pf(expf(z));
    decay[row * 16 + mycol] = expf(-expf(Alog[mycol]) * sp);
}

// ---------------------------------------------------------------------------
// Gated delta rule recurrence, time-tiled with cp.async.
// 256 CTAs = (b,h) x 8 dv-blocks of 16; 128 threads: dkg=tid&7, dvi=tid>>3.
// 2 CTAs/SM -> independent barrier domains hide shuffle/LDS latency.
// ---------------------------------------------------------------------------
#define TT 16
__global__ void __launch_bounds__(128, 2) recur_kernel(
    const float* __restrict__ qn, const float* __restrict__ kn,
    const float* __restrict__ v, const float* __restrict__ decay,
    const float* __restrict__ beta, float* __restrict__ o)
{
    __shared__ float qt[2][TT * 128];
    __shared__ float kt[2][TT * 128];
    __shared__ float vt[2][TT * 16];
    __shared__ float gt[2][TT];
    __shared__ float bt[2][TT];
    __shared__ float ob[TT * 16];

    const int bx = blockIdx.x;
    const int bh = bx >> 3;
    const int dvblk = bx & 7;              // 8 blocks of 16 dv
    const int b = bh >> 4;
    const int h = bh & 15;
    const int tid = threadIdx.x;
    const int dkg = tid & 7;
    const int dvi = tid >> 3;              // 0..15

    const size_t row0 = (size_t)b * 2048;
    const float* qrow = qn + row0 * 2048 + h * 128;
    const float* krow = kn + row0 * 2048 + h * 128;
    const float* vrow = v + row0 * 2048 + h * 128 + dvblk * 16;
    const float* grow = decay + row0 * 16 + h;
    const float* brow = beta + row0 * 16 + h;
    float* obase = o + row0 * 2048 + h * 128 + dvblk * 16;

    float S[16];
#pragma unroll
    for (int i = 0; i < 16; ++i) S[i] = 0.f;

    auto issue_tile = [&](int tt, int buf) {
        const int t0 = tt * TT;
#pragma unroll
        for (int j = 0; j < 4; ++j) {
            int c = tid + j * 128;
            int stp = c >> 5, of = c & 31;
            cp16(smem_u32(&qt[buf][stp * 128 + of * 4]),
                 qrow + (size_t)(t0 + stp) * 2048 + of * 4);
            cp16(smem_u32(&kt[buf][stp * 128 + of * 4]),
                 krow + (size_t)(t0 + stp) * 2048 + of * 4);
        }
        if (tid < 64) {
            int stp = tid >> 2, of = tid & 3;
            cp16(smem_u32(&vt[buf][stp * 16 + of * 4]),
                 vrow + (size_t)(t0 + stp) * 2048 + of * 4);
        } else if (tid < 80) {
            int i = tid - 64;
            cp4(smem_u32(&gt[buf][i]), grow + (size_t)(t0 + i) * 16);
        } else if (tid < 96) {
            int i = tid - 80;
            cp4(smem_u32(&bt[buf][i]), brow + (size_t)(t0 + i) * 16);
        }
    };

    issue_tile(0, 0);
    asm volatile("cp.async.commit_group;");

    const int NT = 2048 / TT;
    for (int tt = 0; tt < NT; ++tt) {
        asm volatile("cp.async.wait_group 0;");
        __syncthreads();
        const int buf = tt & 1;
        if (tt + 1 < NT) issue_tile(tt + 1, buf ^ 1);
        asm volatile("cp.async.commit_group;");

#pragma unroll 4
        for (int stp = 0; stp < TT; ++stp) {
            float qv[16], kv[16];
#pragma unroll
            for (int j = 0; j < 4; ++j) {
                float4 a = *(const float4*)&qt[buf][stp * 128 + (dkg + 8 * j) * 4];
                qv[j * 4 + 0] = a.x; qv[j * 4 + 1] = a.y; qv[j * 4 + 2] = a.z; qv[j * 4 + 3] = a.w;
                float4 c = *(const float4*)&kt[buf][stp * 128 + (dkg + 8 * j) * 4];
                kv[j * 4 + 0] = c.x; kv[j * 4 + 1] = c.y; kv[j * 4 + 2] = c.z; kv[j * 4 + 3] = c.w;
            }
            float o0 = 0.f, o1 = 0.f, s0 = 0.f, s1 = 0.f;
#pragma unroll
            for (int i = 0; i < 16; i += 2) {
                o0 = fmaf(S[i],     qv[i],     o0);
                o1 = fmaf(S[i + 1], qv[i + 1], o1);
                s0 = fmaf(S[i],     kv[i],     s0);
                s1 = fmaf(S[i + 1], kv[i + 1], s1);
            }
            float ot = o0 + o1, sk = s0 + s1;
#pragma unroll
            for (int m = 4; m >= 1; m >>= 1) {
                ot += __shfl_xor_sync(0xffffffffu, ot, m);
                sk += __shfl_xor_sync(0xffffffffu, sk, m);
            }
            const float gv = gt[buf][stp];
            const float bv = bt[buf][stp];
            const float vv = vt[buf][stp * 16 + dvi];
            const float ccc = bv * (vv - sk);
#pragma unroll
            for (int i = 0; i < 16; ++i)
                S[i] = fmaf(ccc, kv[i], S[i] * gv);
            if (dkg == 0) ob[stp * 16 + dvi] = ot;
        }
        __syncthreads();
        if (tid < 64) {
            int stp = tid >> 2, of = tid & 3;
            float4 val = *(const float4*)&ob[stp * 16 + of * 4];
            *(float4*)(obase + (size_t)(tt * TT + stp) * 2048 + of * 4) = val;
        }
    }
}

// ---------------------------------------------------------------------------
// Gated RMSNorm -> split bf16 directly
// ---------------------------------------------------------------------------
__global__ void __launch_bounds__(256) rmsgate_kernel(
    const float* __restrict__ o, const float* __restrict__ xg,
    const float* __restrict__ nw,
    __nv_bfloat16* __restrict__ H, __nv_bfloat16* __restrict__ L)
{
    int u = blockIdx.x * 8 + (threadIdx.x >> 5);
    int lane = threadIdx.x & 31;
    size_t base = (size_t)u * 128 + lane * 4;
    float4 a = *(const float4*)(o + base);
    float ss = a.x * a.x + a.y * a.y + a.z * a.z + a.w * a.w;
#pragma unroll
    for (int m = 16; m >= 1; m >>= 1) ss += __shfl_xor_sync(0xffffffffu, ss, m);
    float r = rsqrtf(ss * (1.f / 128.f) + 1e-6f);
    float4 g = *(const float4*)(xg + base);
    float4 w = *(const float4*)(nw + lane * 4);
    float4 out;
    out.x = a.x * r * w.x * (g.x * sigmoidf_(g.x));
    out.y = a.y * r * w.y * (g.y * sigmoidf_(g.y));
    out.z = a.z * r * w.z * (g.z * sigmoidf_(g.z));
    out.w = a.w * r * w.w * (g.w * sigmoidf_(g.w));
    split4_store(out, H, L, base);
}

// ---------------------------------------------------------------------------
extern "C" void kernel_launch(void* const* d_in, const int* in_sizes, int n_in,
                              void* d_out, int out_size)
{
    const float* x    = (const float*)d_in[0];
    const float* Wq   = (const float*)d_in[1];
    const float* Wk   = (const float*)d_in[2];
    const float* Wv   = (const float*)d_in[3];
    const float* Wb   = (const float*)d_in[4];
    const float* Wa   = (const float*)d_in[5];
    const float* dtb  = (const float*)d_in[6];
    const float* Alog = (const float*)d_in[7];
    const float* W1   = (const float*)d_in[8];
    const float* W2   = (const float*)d_in[9];
    const float* b2   = (const float*)d_in[10];
    const float* nw   = (const float*)d_in[11];
    const float* Wg   = (const float*)d_in[12];
    const float* Wo   = (const float*)d_in[13];
    float* out = (float*)d_out;

    float *q, *k, *v, *v2, *o, *xg, *beta, *decay;
    __nv_bfloat16 *wth, *wtl, *p0h, *p0l, *pqh, *pql;
    cudaGetSymbolAddress((void**)&q,     g_q);
    cudaGetSymbolAddress((void**)&k,     g_k);
    cudaGetSymbolAddress((void**)&v,     g_v);
    cudaGetSymbolAddress((void**)&v2,    g_v2);
    cudaGetSymbolAddress((void**)&o,     g_o);
    cudaGetSymbolAddress((void**)&xg,    g_xg);
    cudaGetSymbolAddress((void**)&beta,  g_beta);
    cudaGetSymbolAddress((void**)&decay, g_decay);
    cudaGetSymbolAddress((void**)&wth,   g_wth);
    cudaGetSymbolAddress((void**)&wtl,   g_wtl);
    cudaGetSymbolAddress((void**)&p0h,   g_p0h);
    cudaGetSymbolAddress((void**)&p0l,   g_p0l);
    cudaGetSymbolAddress((void**)&pqh,   g_pqh);
    cudaGetSymbolAddress((void**)&pql,   g_pql);

    const int SMEM = 81920;
    cudaFuncSetAttribute(gemm_cp, cudaFuncAttributeMaxDynamicSharedMemorySize, SMEM);

    // 0) weight prep
    {
        PrepBatch pb{};
        pb.W[0] = Wq;  pb.off[0] = OFF_Q;
        pb.W[1] = Wk;  pb.off[1] = OFF_K;
        pb.W[2] = Wv;  pb.off[2] = OFF_V;
        pb.W[3] = Wg;  pb.off[3] = OFF_G;
        pb.W[4] = Wo;  pb.off[4] = OFF_WO;
        prep_kernel<<<dim3(64, 64, 5), 256>>>(pb, wth, wtl, 2048, 2048);
        PrepBatch p1{};
        p1.W[0] = W1;  p1.off[0] = OFF_W1;
        prep_kernel<<<dim3(64, 128, 1), 256>>>(p1, wth, wtl, 2048, 4096);
        PrepBatch p2{};
        p2.W[0] = W2;  p2.off[0] = OFF_W2;
        prep_kernel<<<dim3(256, 64, 1), 256>>>(p2, wth, wtl, 8192, 2048);
    }
    // 0b) split x
    split_kernel<<<8192, 256>>>(x, p0h, p0l);
    // 1) fused projections: q,k (EPI1), v,xg (EPI0)
    {
        GB bt{};
        for (int z = 0; z < 4; ++z) { bt.Ah[z] = p0h; bt.Al[z] = p0l; }
        bt.Bh[0] = wth + OFF_Q; bt.Bh[1] = wth + OFF_K; bt.Bh[2] = wth + OFF_V; bt.Bh[3] = wth + OFF_G;
        bt.Bl[0] = wtl + OFF_Q; bt.Bl[1] = wtl + OFF_K; bt.Bl[2] = wtl + OFF_V; bt.Bl[3] = wtl + OFF_G;
        bt.C[0] = q; bt.C[1] = k; bt.C[2] = v; bt.C[3] = xg;
        bt.epi[0] = 1; bt.epi[1] = 1; bt.epi[2] = 0; bt.epi[3] = 0;
        bt.eh[0] = pqh; bt.el[0] = pql; bt.estride[0] = 4096; bt.ecol[0] = 0;
        bt.eh[1] = pqh; bt.el[1] = pql; bt.estride[1] = 4096; bt.ecol[1] = 2048;
        gemm_cp<<<dim3(16, 32, 4), 256, SMEM>>>(bt, 4096, 2048, 2048);
    }
    betag_kernel<<<256, 256>>>(x, Wb, Wa, dtb, Alog, beta, decay);
    // 2) generator layer 1 (K=4096), EPI2: silu + split
    {
        GB bt{};
        bt.Ah[0] = pqh; bt.Al[0] = pql;
        bt.Bh[0] = wth + OFF_W1; bt.Bl[0] = wtl + OFF_W1;
        bt.C[0] = nullptr;
        bt.epi[0] = 2;
        bt.eh[0] = p0h; bt.el[0] = p0l; bt.estride[0] = 2048; bt.ecol[0] = 0;
        gemm_cp<<<dim3(16, 32, 1), 256, SMEM>>>(bt, 4096, 2048, 4096);
    }
    // 3) generator layer 2 + bias + dynamic conv + SiLU -> v2 (EPI3)
    {
        GB bt{};
        bt.Ah[0] = p0h; bt.Al[0] = p0l;
        bt.Bh[0] = wth + OFF_W2; bt.Bl[0] = wtl + OFF_W2;
        bt.C[0] = v2;
        bt.epi[0] = 3;
        bt.vsrc = v; bt.bias = b2;
        gemm_cp<<<dim3(64, 32, 1), 256, SMEM>>>(bt, 4096, 8192, 2048);
    }
    // 4) recurrence (256 CTAs x 128 threads, 2/SM)
    recur_kernel<<<256, 128>>>(q, k, v2, decay, beta, o);
    // 5) gated RMSNorm -> og split
    rmsgate_kernel<<<8192, 256>>>(o, xg, nw, p0h, p0l);
    // 6) output projection
    {
        GB bt{};
        bt.Ah[0] = p0h; bt.Al[0] = p0l;
        bt.Bh[0] = wth + OFF_WO; bt.Bl[0] = wtl + OFF_WO;
        bt.C[0] = out;
        bt.epi[0] = 0;
        gemm_cp<<<dim3(16, 32, 1), 256, SMEM>>>(bt, 4096, 2048, 2048);
    }
}

// round 10
// speedup vs baseline: 1.1712x; 1.1353x over previous
#include <cuda_runtime.h>
#include <cuda_bf16.h>
#include <mma.h>
#include <cstdint>

using namespace nvcuda;

// ---------------------------------------------------------------------------
// Dims (fixed): B=2, T=2048, HID=2048, H=16, DK=DV=128, W=4; rows = B*T = 4096
// Toolchain lowers to compute_103 PTX (no tcgen05). Stay sm_80-portable.
// GEMM: CTA 128x128, 4 warps of 64x64 (low smem traffic), 2 CTAs/SM,
// 2-stage cp.async, grid 512 (good wave quantization).
// ---------------------------------------------------------------------------

__device__ float g_q   [4096ll * 2048];   // NORMALIZED q
__device__ float g_k   [4096ll * 2048];   // NORMALIZED k
__device__ float g_v   [4096ll * 2048];
__device__ float g_v2  [4096ll * 2048];   // silu(conv(v))
__device__ float g_o   [4096ll * 2048];
__device__ float g_xg  [4096ll * 2048];
__device__ float g_beta [4096 * 16];
__device__ float g_decay[4096 * 16];

#define MELEM 4194304ll
#define OFF_Q   (0ll)
#define OFF_K   (1ll * MELEM)
#define OFF_V   (2ll * MELEM)
#define OFF_G   (3ll * MELEM)
#define OFF_W1  (4ll * MELEM)
#define OFF_WO  (6ll * MELEM)
#define OFF_W2  (7ll * MELEM)
__device__ __nv_bfloat16 g_wth[11ll * MELEM];
__device__ __nv_bfloat16 g_wtl[11ll * MELEM];

__device__ __nv_bfloat16 g_p0h[4096ll * 2048];
__device__ __nv_bfloat16 g_p0l[4096ll * 2048];
__device__ __nv_bfloat16 g_pqh[4096ll * 4096];
__device__ __nv_bfloat16 g_pql[4096ll * 4096];

__device__ __forceinline__ float sigmoidf_(float x) { return 1.f / (1.f + expf(-x)); }

__device__ __forceinline__ uint32_t smem_u32(const void* p) {
    uint32_t a;
    asm("{ .reg .u64 t; cvta.to.shared.u64 t, %1; cvt.u32.u64 %0, t; }" : "=r"(a) : "l"(p));
    return a;
}
__device__ __forceinline__ void cp16(uint32_t so, const void* g) {
    asm volatile("cp.async.cg.shared.global [%0], [%1], 16;" :: "r"(so), "l"(g));
}
__device__ __forceinline__ void cp4(uint32_t so, const void* g) {
    asm volatile("cp.async.ca.shared.global [%0], [%1], 4;" :: "r"(so), "l"(g));
}

__device__ __forceinline__ void split2(float x, float y, uint32_t& hu, uint32_t& lu) {
    __nv_bfloat16 hx = __float2bfloat16_rn(x), hy = __float2bfloat16_rn(y);
    __nv_bfloat16 lx = __float2bfloat16_rn(x - __bfloat162float(hx));
    __nv_bfloat16 ly = __float2bfloat16_rn(y - __bfloat162float(hy));
    __nv_bfloat162 h(hx, hy), l(lx, ly);
    hu = *(uint32_t*)&h;
    lu = *(uint32_t*)&l;
}
__device__ __forceinline__ void split4_store(
    float4 v, __nv_bfloat16* __restrict__ h, __nv_bfloat16* __restrict__ l, size_t i)
{
    uint2 hu, lu;
    split2(v.x, v.y, hu.x, lu.x);
    split2(v.z, v.w, hu.y, lu.y);
    *(uint2*)(h + i) = hu;
    *(uint2*)(l + i) = lu;
}

// ---------------------------------------------------------------------------
// Weight prep
// ---------------------------------------------------------------------------
struct PrepBatch { const float* W[5]; long long off[5]; };

__global__ void __launch_bounds__(256) prep_kernel(
    PrepBatch pb, __nv_bfloat16* __restrict__ Th, __nv_bfloat16* __restrict__ Tl,
    int N, int Kd)
{
    __shared__ float s[32][33];
    const float* W = pb.W[blockIdx.z];
    const long long base = pb.off[blockIdx.z];
    const int n0 = blockIdx.x * 32, k0 = blockIdx.y * 32;
    const int tid = threadIdx.x;
#pragma unroll
    for (int j = 0; j < 4; ++j) {
        int lin = tid + j * 256;
        int kk = lin >> 5, nn = lin & 31;
        s[kk][nn] = W[(size_t)(k0 + kk) * N + n0 + nn];
    }
    __syncthreads();
#pragma unroll
    for (int j = 0; j < 4; ++j) {
        int lin = tid + j * 256;
        int nn = lin >> 5, kk = lin & 31;
        float v = s[kk][nn];
        __nv_bfloat16 h = __float2bfloat16_rn(v);
        __nv_bfloat16 l = __float2bfloat16_rn(v - __bfloat162float(h));
        size_t o = (size_t)base + (size_t)(n0 + nn) * Kd + k0 + kk;
        Th[o] = h;
        Tl[o] = l;
    }
}

__global__ void __launch_bounds__(256) split_kernel(
    const float* __restrict__ s, __nv_bfloat16* __restrict__ h, __nv_bfloat16* __restrict__ l)
{
    size_t i = ((size_t)blockIdx.x * 256 + threadIdx.x) * 4;
    split4_store(*(const float4*)(s + i), h, l, i);
}

// ---------------------------------------------------------------------------
// Split-bf16 HMMA GEMM, CTA 128x128, 4 warps (64x64 each), 2-stage cp.async.
// ---------------------------------------------------------------------------
struct GB {
    const __nv_bfloat16* Ah[4]; const __nv_bfloat16* Al[4];
    const __nv_bfloat16* Bh[4]; const __nv_bfloat16* Bl[4];
    float* C[4];
    int epi[4];
    __nv_bfloat16* eh[4]; __nv_bfloat16* el[4];
    long long estride[4]; long long ecol[4];
    const float* vsrc; const float* bias;
};

#define EPS 140

__global__ void __launch_bounds__(128, 2) gemm_cp(
    GB bt, int M, int N, int K)
{
    extern __shared__ __align__(16) char dsm[];
    __shared__ float sc[128];
    const int tid = threadIdx.x;
    const int wid = tid >> 5;          // 0..3
    const int lane = tid & 31;
    const int wm  = wid >> 1;          // 0..1
    const int wn  = wid & 1;           // 0..1
    const int m0  = blockIdx.y << 7;
    const int n0  = blockIdx.x << 7;
    const int z   = blockIdx.z;
    const __nv_bfloat16* __restrict__ Ah = bt.Ah[z];
    const __nv_bfloat16* __restrict__ Al = bt.Al[z];
    const __nv_bfloat16* __restrict__ Bh = bt.Bh[z];
    const __nv_bfloat16* __restrict__ Bl = bt.Bl[z];
    float* __restrict__ C = bt.C[z];

    const uint32_t sbase = smem_u32(dsm);
    const int cr = tid >> 2, c16 = tid & 3;     // copy row base (0..31), 16B col

    auto issue = [&](int s, int kc) {
        const uint32_t sb = sbase + s * 40960;
        const size_t ka = (size_t)kc * 32 + c16 * 8;
#pragma unroll
        for (int j = 0; j < 4; ++j) {
            int r = cr + j * 32;
            uint32_t so = sb + r * 80 + c16 * 16;
            cp16(so,         Ah + (size_t)(m0 + r) * K + ka);
            cp16(so + 10240, Al + (size_t)(m0 + r) * K + ka);
            cp16(so + 20480, Bh + (size_t)(n0 + r) * K + ka);
            cp16(so + 30720, Bl + (size_t)(n0 + r) * K + ka);
        }
    };

    wmma::fragment<wmma::accumulator, 16, 16, 16, float> acc[4][4];
#pragma unroll
    for (int i = 0; i < 4; ++i)
#pragma unroll
        for (int j = 0; j < 4; ++j) wmma::fill_fragment(acc[i][j], 0.f);

    issue(0, 0);
    asm volatile("cp.async.commit_group;");

    const int NC = K >> 5;
    for (int c = 0; c < NC; ++c) {
        const int s = c & 1;
        if (c + 1 < NC) issue(s ^ 1, c + 1);
        asm volatile("cp.async.commit_group;");
        asm volatile("cp.async.wait_group 1;");
        __syncthreads();

        const __nv_bfloat16* ah = (const __nv_bfloat16*)(dsm + s * 40960);
        const __nv_bfloat16* al = (const __nv_bfloat16*)(dsm + s * 40960 + 10240);
        const __nv_bfloat16* bh = (const __nv_bfloat16*)(dsm + s * 40960 + 20480);
        const __nv_bfloat16* bl = (const __nv_bfloat16*)(dsm + s * 40960 + 30720);

#pragma unroll
        for (int kk = 0; kk < 2; ++kk) {
            wmma::fragment<wmma::matrix_b, 16, 16, 16, __nv_bfloat16, wmma::col_major> bfh[4], bfl[4];
#pragma unroll
            for (int ni = 0; ni < 4; ++ni) {
                wmma::load_matrix_sync(bfh[ni], bh + (wn * 64 + ni * 16) * 40 + kk * 16, 40);
                wmma::load_matrix_sync(bfl[ni], bl + (wn * 64 + ni * 16) * 40 + kk * 16, 40);
            }
#pragma unroll
            for (int mi = 0; mi < 4; ++mi) {
                wmma::fragment<wmma::matrix_a, 16, 16, 16, __nv_bfloat16, wmma::row_major> afh, afl;
                wmma::load_matrix_sync(afh, ah + (wm * 64 + mi * 16) * 40 + kk * 16, 40);
                wmma::load_matrix_sync(afl, al + (wm * 64 + mi * 16) * 40 + kk * 16, 40);
#pragma unroll
                for (int ni = 0; ni < 4; ++ni) {
                    wmma::mma_sync(acc[mi][ni], afh, bfl[ni], acc[mi][ni]);
                    wmma::mma_sync(acc[mi][ni], afl, bfh[ni], acc[mi][ni]);
                    wmma::mma_sync(acc[mi][ni], afh, bfh[ni], acc[mi][ni]);
                }
            }
        }
        __syncthreads();
    }

    const int epi_mode = bt.epi[z];
    if (epi_mode == 0) {
#pragma unroll
        for (int mi = 0; mi < 4; ++mi)
#pragma unroll
            for (int ni = 0; ni < 4; ++ni)
                wmma::store_matrix_sync(C + (size_t)(m0 + wm * 64 + mi * 16) * N + n0 + wn * 64 + ni * 16,
                                        acc[mi][ni], N, wmma::mem_row_major);
        return;
    }

    // stage acc tile (128x128) to smem
    float* ep = (float*)dsm;
#pragma unroll
    for (int mi = 0; mi < 4; ++mi)
#pragma unroll
        for (int ni = 0; ni < 4; ++ni)
            wmma::store_matrix_sync(ep + (wm * 64 + mi * 16) * EPS + wn * 64 + ni * 16,
                                    acc[mi][ni], EPS, wmma::mem_row_major);
    __syncthreads();

    if (epi_mode == 1) {
        // per-row L2 norm (tile N-width 128 == one head); one thread per row
        {
            float ss = 0.f;
#pragma unroll 8
            for (int i = 0; i < 128; ++i) {
                float v = ep[tid * EPS + i];
                ss = fmaf(v, v, ss);
            }
            sc[tid] = 1.f / fmaxf(sqrtf(ss), 1e-12f);
        }
        __syncthreads();
        const int r = tid;
        const float s = sc[r];
        const size_t row = m0 + r;
        float* Cp = C + row * N + n0;
        __nv_bfloat16* H = bt.eh[z] + row * bt.estride[z] + bt.ecol[z] + n0;
        __nv_bfloat16* L = bt.el[z] + row * bt.estride[z] + bt.ecol[z] + n0;
#pragma unroll 8
        for (int j = 0; j < 32; ++j) {
            float4 v = *(float4*)(ep + r * EPS + j * 4);
            split4_store(v, H, L, j * 4);
            v.x *= s; v.y *= s; v.z *= s; v.w *= s;
            *(float4*)(Cp + j * 4) = v;
        }
    } else if (epi_mode == 2) {
        const int r = tid;
        const size_t row = m0 + r;
        __nv_bfloat16* H = bt.eh[z] + row * bt.estride[z] + n0;
        __nv_bfloat16* L = bt.el[z] + row * bt.estride[z] + n0;
#pragma unroll 8
        for (int j = 0; j < 32; ++j) {
            float4 v = *(float4*)(ep + r * EPS + j * 4);
            v.x = v.x * sigmoidf_(v.x);
            v.y = v.y * sigmoidf_(v.y);
            v.z = v.z * sigmoidf_(v.z);
            v.w = v.w * sigmoidf_(v.w);
            split4_store(v, H, L, j * 4);
        }
    } else {
        // EPI 3: dynamic conv. Tile = kern[rows][32 d x 4 w]; d = n0/4 + lane.
        const int d = (n0 >> 2) + lane;
        const float4 bb = *(const float4*)(bt.bias + n0 + lane * 4);
        const float* vcol = bt.vsrc + d;
        const int rbase = m0 + wid * 32;
        float vw0, vw1, vw2, vw3;
        {
            int tl = rbase & 2047;
            vw0 = (tl >= 3) ? vcol[(size_t)(rbase - 3) * 2048] : 0.f;
            vw1 = (tl >= 2) ? vcol[(size_t)(rbase - 2) * 2048] : 0.f;
            vw2 = (tl >= 1) ? vcol[(size_t)(rbase - 1) * 2048] : 0.f;
        }
#pragma unroll
        for (int i = 0; i < 32; ++i) {
            const int row = rbase + i;
            const int tl = row & 2047;
            vw3 = vcol[(size_t)row * 2048];
            float4 kf = *(const float4*)(ep + (wid * 32 + i) * EPS + lane * 4);
            kf.x += bb.x; kf.y += bb.y; kf.z += bb.z; kf.w += bb.w;
            float a0 = (tl >= 3) ? vw0 : 0.f;
            float a1 = (tl >= 2) ? vw1 : 0.f;
            float a2 = (tl >= 1) ? vw2 : 0.f;
            float acc2 = kf.x * a0 + kf.y * a1 + kf.z * a2 + kf.w * vw3;
            C[(size_t)row * 2048 + d] = acc2 * sigmoidf_(acc2);
            vw0 = vw1; vw1 = vw2; vw2 = vw3;
        }
    }
}

// ---------------------------------------------------------------------------
// beta / decay
// ---------------------------------------------------------------------------
__global__ void __launch_bounds__(256) betag_kernel(
    const float* __restrict__ x, const float* __restrict__ Wb, const float* __restrict__ Wa,
    const float* __restrict__ dtb, const float* __restrict__ Alog,
    float* __restrict__ beta, float* __restrict__ decay)
{
    __shared__ float xs[16][128];
    __shared__ float wbs[128 * 17];
    __shared__ float was[128 * 17];
    const int tid = threadIdx.x;
    const int myrow = tid >> 4, mycol = tid & 15;
    const int r0 = blockIdx.x * 16;
    float pb = 0.f, pa = 0.f;
    for (int ch = 0; ch < 16; ++ch) {
        __syncthreads();
#pragma unroll
        for (int j = 0; j < 8; ++j) {
            int lin = tid + j * 256;
            int rr = lin >> 7, cc = lin & 127;
            xs[rr][cc] = x[(size_t)(r0 + rr) * 2048 + ch * 128 + cc];
            int wi = lin >> 4, wc = lin & 15;
            wbs[wi * 17 + wc] = Wb[(size_t)ch * 2048 + lin];
            was[wi * 17 + wc] = Wa[(size_t)ch * 2048 + lin];
        }
        __syncthreads();
#pragma unroll 8
        for (int i = 0; i < 128; ++i) {
            float xv = xs[myrow][i];
            pb = fmaf(xv, wbs[i * 17 + mycol], pb);
            pa = fmaf(xv, was[i * 17 + mycol], pa);
        }
    }
    int row = r0 + myrow;
    beta[row * 16 + mycol] = 1.f / (1.f + expf(-pb));
    float z = pa + dtb[mycol];
    float sp = (z > 20.f) ? z : log1pf(expf(z));
    decay[row * 16 + mycol] = expf(-expf(Alog[mycol]) * sp);
}

// ---------------------------------------------------------------------------
// Gated delta rule recurrence, time-tiled with cp.async (R7 best-measured cfg)
// ---------------------------------------------------------------------------
#define TT 16
__global__ void __launch_bounds__(256, 1) recur_kernel(
    const float* __restrict__ qn, const float* __restrict__ kn,
    const float* __restrict__ v, const float* __restrict__ decay,
    const float* __restrict__ beta, float* __restrict__ o)
{
    __shared__ float qt[2][TT * 128];
    __shared__ float kt[2][TT * 128];
    __shared__ float vt[2][TT * 32];
    __shared__ float gt[2][TT];
    __shared__ float bt[2][TT];
    __shared__ float ob[TT * 32];

    const int bx = blockIdx.x;
    const int bh = bx >> 2;
    const int dvblk = bx & 3;
    const int b = bh >> 4;
    const int h = bh & 15;
    const int tid = threadIdx.x;
    const int dkg = tid & 7;
    const int dvi = tid >> 3;

    const size_t row0 = (size_t)b * 2048;
    const float* qrow = qn + row0 * 2048 + h * 128;
    const float* krow = kn + row0 * 2048 + h * 128;
    const float* vrow = v + row0 * 2048 + h * 128 + dvblk * 32;
    const float* grow = decay + row0 * 16 + h;
    const float* brow = beta + row0 * 16 + h;
    float* obase = o + row0 * 2048 + h * 128 + dvblk * 32;

    float S[16];
#pragma unroll
    for (int i = 0; i < 16; ++i) S[i] = 0.f;

    auto issue_tile = [&](int tt, int buf) {
        const int t0 = tt * TT;
#pragma unroll
        for (int j = 0; j < 2; ++j) {
            int c = tid + j * 256;
            int stp = c >> 5, of = c & 31;
            cp16(smem_u32(&qt[buf][stp * 128 + of * 4]),
                 qrow + (size_t)(t0 + stp) * 2048 + of * 4);
            cp16(smem_u32(&kt[buf][stp * 128 + of * 4]),
                 krow + (size_t)(t0 + stp) * 2048 + of * 4);
        }
        if (tid < 128) {
            int stp = tid >> 3, of = tid & 7;
            cp16(smem_u32(&vt[buf][stp * 32 + of * 4]),
                 vrow + (size_t)(t0 + stp) * 2048 + of * 4);
        } else if (tid < 144) {
            int i = tid - 128;
            cp4(smem_u32(&gt[buf][i]), grow + (size_t)(t0 + i) * 16);
        } else if (tid < 160) {
            int i = tid - 144;
            cp4(smem_u32(&bt[buf][i]), brow + (size_t)(t0 + i) * 16);
        }
    };

    issue_tile(0, 0);
    asm volatile("cp.async.commit_group;");

    const int NT = 2048 / TT;
    for (int tt = 0; tt < NT; ++tt) {
        asm volatile("cp.async.wait_group 0;");
        __syncthreads();
        const int buf = tt & 1;
        if (tt + 1 < NT) issue_tile(tt + 1, buf ^ 1);
        asm volatile("cp.async.commit_group;");

#pragma unroll 4
        for (int stp = 0; stp < TT; ++stp) {
            float qv[16], kv[16];
#pragma unroll
            for (int j = 0; j < 4; ++j) {
                float4 a = *(const float4*)&qt[buf][stp * 128 + (dkg + 8 * j) * 4];
                qv[j * 4 + 0] = a.x; qv[j * 4 + 1] = a.y; qv[j * 4 + 2] = a.z; qv[j * 4 + 3] = a.w;
                float4 c = *(const float4*)&kt[buf][stp * 128 + (dkg + 8 * j) * 4];
                kv[j * 4 + 0] = c.x; kv[j * 4 + 1] = c.y; kv[j * 4 + 2] = c.z; kv[j * 4 + 3] = c.w;
            }
            float o0 = 0.f, o1 = 0.f, s0 = 0.f, s1 = 0.f;
#pragma unroll
            for (int i = 0; i < 16; i += 2) {
                o0 = fmaf(S[i],     qv[i],     o0);
                o1 = fmaf(S[i + 1], qv[i + 1], o1);
                s0 = fmaf(S[i],     kv[i],     s0);
                s1 = fmaf(S[i + 1], kv[i + 1], s1);
            }
            float ot = o0 + o1, sk = s0 + s1;
#pragma unroll
            for (int m = 4; m >= 1; m >>= 1) {
                ot += __shfl_xor_sync(0xffffffffu, ot, m);
                sk += __shfl_xor_sync(0xffffffffu, sk, m);
            }
            const float gv = gt[buf][stp];
            const float bv = bt[buf][stp];
            const float vv = vt[buf][stp * 32 + dvi];
            const float ccc = bv * (vv - sk);
#pragma unroll
            for (int i = 0; i < 16; ++i)
                S[i] = fmaf(ccc, kv[i], S[i] * gv);
            if (dkg == 0) ob[stp * 32 + dvi] = ot;
        }
        __syncthreads();
        if (tid < 128) {
            int stp = tid >> 3, of = tid & 7;
            float4 val = *(const float4*)&ob[stp * 32 + of * 4];
            *(float4*)(obase + (size_t)(tt * TT + stp) * 2048 + of * 4) = val;
        }
    }
}

// ---------------------------------------------------------------------------
// Gated RMSNorm -> split bf16 directly
// ---------------------------------------------------------------------------
__global__ void __launch_bounds__(256) rmsgate_kernel(
    const float* __restrict__ o, const float* __restrict__ xg,
    const float* __restrict__ nw,
    __nv_bfloat16* __restrict__ H, __nv_bfloat16* __restrict__ L)
{
    int u = blockIdx.x * 8 + (threadIdx.x >> 5);
    int lane = threadIdx.x & 31;
    size_t base = (size_t)u * 128 + lane * 4;
    float4 a = *(const float4*)(o + base);
    float ss = a.x * a.x + a.y * a.y + a.z * a.z + a.w * a.w;
#pragma unroll
    for (int m = 16; m >= 1; m >>= 1) ss += __shfl_xor_sync(0xffffffffu, ss, m);
    float r = rsqrtf(ss * (1.f / 128.f) + 1e-6f);
    float4 g = *(const float4*)(xg + base);
    float4 w = *(const float4*)(nw + lane * 4);
    float4 out;
    out.x = a.x * r * w.x * (g.x * sigmoidf_(g.x));
    out.y = a.y * r * w.y * (g.y * sigmoidf_(g.y));
    out.z = a.z * r * w.z * (g.z * sigmoidf_(g.z));
    out.w = a.w * r * w.w * (g.w * sigmoidf_(g.w));
    split4_store(out, H, L, base);
}

// ---------------------------------------------------------------------------
extern "C" void kernel_launch(void* const* d_in, const int* in_sizes, int n_in,
                              void* d_out, int out_size)
{
    const float* x    = (const float*)d_in[0];
    const float* Wq   = (const float*)d_in[1];
    const float* Wk   = (const float*)d_in[2];
    const float* Wv   = (const float*)d_in[3];
    const float* Wb   = (const float*)d_in[4];
    const float* Wa   = (const float*)d_in[5];
    const float* dtb  = (const float*)d_in[6];
    const float* Alog = (const float*)d_in[7];
    const float* W1   = (const float*)d_in[8];
    const float* W2   = (const float*)d_in[9];
    const float* b2   = (const float*)d_in[10];
    const float* nw   = (const float*)d_in[11];
    const float* Wg   = (const float*)d_in[12];
    const float* Wo   = (const float*)d_in[13];
    float* out = (float*)d_out;

    float *q, *k, *v, *v2, *o, *xg, *beta, *decay;
    __nv_bfloat16 *wth, *wtl, *p0h, *p0l, *pqh, *pql;
    cudaGetSymbolAddress((void**)&q,     g_q);
    cudaGetSymbolAddress((void**)&k,     g_k);
    cudaGetSymbolAddress((void**)&v,     g_v);
    cudaGetSymbolAddress((void**)&v2,    g_v2);
    cudaGetSymbolAddress((void**)&o,     g_o);
    cudaGetSymbolAddress((void**)&xg,    g_xg);
    cudaGetSymbolAddress((void**)&beta,  g_beta);
    cudaGetSymbolAddress((void**)&decay, g_decay);
    cudaGetSymbolAddress((void**)&wth,   g_wth);
    cudaGetSymbolAddress((void**)&wtl,   g_wtl);
    cudaGetSymbolAddress((void**)&p0h,   g_p0h);
    cudaGetSymbolAddress((void**)&p0l,   g_p0l);
    cudaGetSymbolAddress((void**)&pqh,   g_pqh);
    cudaGetSymbolAddress((void**)&pql,   g_pql);

    const int SMEM = 81920;
    cudaFuncSetAttribute(gemm_cp, cudaFuncAttributeMaxDynamicSharedMemorySize, SMEM);

    // 0) weight prep
    {
        PrepBatch pb{};
        pb.W[0] = Wq;  pb.off[0] = OFF_Q;
        pb.W[1] = Wk;  pb.off[1] = OFF_K;
        pb.W[2] = Wv;  pb.off[2] = OFF_V;
        pb.W[3] = Wg;  pb.off[3] = OFF_G;
        pb.W[4] = Wo;  pb.off[4] = OFF_WO;
        prep_kernel<<<dim3(64, 64, 5), 256>>>(pb, wth, wtl, 2048, 2048);
        PrepBatch p1{};
        p1.W[0] = W1;  p1.off[0] = OFF_W1;
        prep_kernel<<<dim3(64, 128, 1), 256>>>(p1, wth, wtl, 2048, 4096);
        PrepBatch p2{};
        p2.W[0] = W2;  p2.off[0] = OFF_W2;
        prep_kernel<<<dim3(256, 64, 1), 256>>>(p2, wth, wtl, 8192, 2048);
    }
    // 0b) split x
    split_kernel<<<8192, 256>>>(x, p0h, p0l);
    // 1) fused projections: q,k (EPI1), v,xg (EPI0)
    {
        GB bt{};
        for (int z = 0; z < 4; ++z) { bt.Ah[z] = p0h; bt.Al[z] = p0l; }
        bt.Bh[0] = wth + OFF_Q; bt.Bh[1] = wth + OFF_K; bt.Bh[2] = wth + OFF_V; bt.Bh[3] = wth + OFF_G;
        bt.Bl[0] = wtl + OFF_Q; bt.Bl[1] = wtl + OFF_K; bt.Bl[2] = wtl + OFF_V; bt.Bl[3] = wtl + OFF_G;
        bt.C[0] = q; bt.C[1] = k; bt.C[2] = v; bt.C[3] = xg;
        bt.epi[0] = 1; bt.epi[1] = 1; bt.epi[2] = 0; bt.epi[3] = 0;
        bt.eh[0] = pqh; bt.el[0] = pql; bt.estride[0] = 4096; bt.ecol[0] = 0;
        bt.eh[1] = pqh; bt.el[1] = pql; bt.estride[1] = 4096; bt.ecol[1] = 2048;
        gemm_cp<<<dim3(16, 32, 4), 128, SMEM>>>(bt, 4096, 2048, 2048);
    }
    betag_kernel<<<256, 256>>>(x, Wb, Wa, dtb, Alog, beta, decay);
    // 2) generator layer 1 (K=4096), EPI2: silu + split
    {
        GB bt{};
        bt.Ah[0] = pqh; bt.Al[0] = pql;
        bt.Bh[0] = wth + OFF_W1; bt.Bl[0] = wtl + OFF_W1;
        bt.C[0] = nullptr;
        bt.epi[0] = 2;
        bt.eh[0] = p0h; bt.el[0] = p0l; bt.estride[0] = 2048; bt.ecol[0] = 0;
        gemm_cp<<<dim3(16, 32, 1), 128, SMEM>>>(bt, 4096, 2048, 4096);
    }
    // 3) generator layer 2 + bias + dynamic conv + SiLU -> v2 (EPI3)
    {
        GB bt{};
        bt.Ah[0] = p0h; bt.Al[0] = p0l;
        bt.Bh[0] = wth + OFF_W2; bt.Bl[0] = wtl + OFF_W2;
        bt.C[0] = v2;
        bt.epi[0] = 3;
        bt.vsrc = v; bt.bias = b2;
        gemm_cp<<<dim3(64, 32, 1), 128, SMEM>>>(bt, 4096, 8192, 2048);
    }
    // 4) recurrence
    recur_kernel<<<128, 256>>>(q, k, v2, decay, beta, o);
    // 5) gated RMSNorm -> og split
    rmsgate_kernel<<<8192, 256>>>(o, xg, nw, p0h, p0l);
    // 6) output projection
    {
        GB bt{};
        bt.Ah[0] = p0h; bt.Al[0] = p0l;
        bt.Bh[0] = wth + OFF_WO; bt.Bl[0] = wtl + OFF_WO;
        bt.C[0] = out;
        bt.epi[0] = 0;
        gemm_cp<<<dim3(16, 32, 1), 128, SMEM>>>(bt, 4096, 2048, 2048);
    }
}

// round 11
// speedup vs baseline: 1.1855x; 1.0122x over previous
#include <cuda_runtime.h>
#include <cuda_bf16.h>
#include <mma.h>
#include <cstdint>

using namespace nvcuda;

// ---------------------------------------------------------------------------
// Dims (fixed): B=2, T=2048, HID=2048, H=16, DK=DV=128, W=4; rows = B*T = 4096
// Toolchain lowers to compute_103 PTX (no tcgen05). Stay sm_80-portable.
// GEMM: CTA 128x128, 4 warps of 64x64, 2 CTAs/SM, 2-stage cp.async,
// ONE barrier per K-chunk.
// ---------------------------------------------------------------------------

__device__ float g_q   [4096ll * 2048];   // NORMALIZED q
__device__ float g_k   [4096ll * 2048];   // NORMALIZED k
__device__ float g_v   [4096ll * 2048];
__device__ float g_v2  [4096ll * 2048];   // silu(conv(v))
__device__ float g_o   [4096ll * 2048];
__device__ float g_xg  [4096ll * 2048];
__device__ float g_beta [4096 * 16];
__device__ float g_decay[4096 * 16];

#define MELEM 4194304ll
#define OFF_Q   (0ll)
#define OFF_K   (1ll * MELEM)
#define OFF_V   (2ll * MELEM)
#define OFF_G   (3ll * MELEM)
#define OFF_W1  (4ll * MELEM)
#define OFF_WO  (6ll * MELEM)
#define OFF_W2  (7ll * MELEM)
__device__ __nv_bfloat16 g_wth[11ll * MELEM];
__device__ __nv_bfloat16 g_wtl[11ll * MELEM];

__device__ __nv_bfloat16 g_p0h[4096ll * 2048];
__device__ __nv_bfloat16 g_p0l[4096ll * 2048];
__device__ __nv_bfloat16 g_pqh[4096ll * 4096];
__device__ __nv_bfloat16 g_pql[4096ll * 4096];

__device__ __forceinline__ float sigmoidf_(float x) { return 1.f / (1.f + expf(-x)); }

__device__ __forceinline__ uint32_t smem_u32(const void* p) {
    uint32_t a;
    asm("{ .reg .u64 t; cvta.to.shared.u64 t, %1; cvt.u32.u64 %0, t; }" : "=r"(a) : "l"(p));
    return a;
}
__device__ __forceinline__ void cp16(uint32_t so, const void* g) {
    asm volatile("cp.async.cg.shared.global [%0], [%1], 16;" :: "r"(so), "l"(g));
}
__device__ __forceinline__ void cp4(uint32_t so, const void* g) {
    asm volatile("cp.async.ca.shared.global [%0], [%1], 4;" :: "r"(so), "l"(g));
}

__device__ __forceinline__ void split2(float x, float y, uint32_t& hu, uint32_t& lu) {
    __nv_bfloat16 hx = __float2bfloat16_rn(x), hy = __float2bfloat16_rn(y);
    __nv_bfloat16 lx = __float2bfloat16_rn(x - __bfloat162float(hx));
    __nv_bfloat16 ly = __float2bfloat16_rn(y - __bfloat162float(hy));
    __nv_bfloat162 h(hx, hy), l(lx, ly);
    hu = *(uint32_t*)&h;
    lu = *(uint32_t*)&l;
}
__device__ __forceinline__ void split4_store(
    float4 v, __nv_bfloat16* __restrict__ h, __nv_bfloat16* __restrict__ l, size_t i)
{
    uint2 hu, lu;
    split2(v.x, v.y, hu.x, lu.x);
    split2(v.z, v.w, hu.y, lu.y);
    *(uint2*)(h + i) = hu;
    *(uint2*)(l + i) = lu;
}

// ---------------------------------------------------------------------------
// Weight prep
// ---------------------------------------------------------------------------
struct PrepBatch { const float* W[5]; long long off[5]; };

__global__ void __launch_bounds__(256) prep_kernel(
    PrepBatch pb, __nv_bfloat16* __restrict__ Th, __nv_bfloat16* __restrict__ Tl,
    int N, int Kd)
{
    __shared__ float s[32][33];
    const float* W = pb.W[blockIdx.z];
    const long long base = pb.off[blockIdx.z];
    const int n0 = blockIdx.x * 32, k0 = blockIdx.y * 32;
    const int tid = threadIdx.x;
#pragma unroll
    for (int j = 0; j < 4; ++j) {
        int lin = tid + j * 256;
        int kk = lin >> 5, nn = lin & 31;
        s[kk][nn] = W[(size_t)(k0 + kk) * N + n0 + nn];
    }
    __syncthreads();
#pragma unroll
    for (int j = 0; j < 4; ++j) {
        int lin = tid + j * 256;
        int nn = lin >> 5, kk = lin & 31;
        float v = s[kk][nn];
        __nv_bfloat16 h = __float2bfloat16_rn(v);
        __nv_bfloat16 l = __float2bfloat16_rn(v - __bfloat162float(h));
        size_t o = (size_t)base + (size_t)(n0 + nn) * Kd + k0 + kk;
        Th[o] = h;
        Tl[o] = l;
    }
}

__global__ void __launch_bounds__(256) split_kernel(
    const float* __restrict__ s, __nv_bfloat16* __restrict__ h, __nv_bfloat16* __restrict__ l)
{
    size_t i = ((size_t)blockIdx.x * 256 + threadIdx.x) * 4;
    split4_store(*(const float4*)(s + i), h, l, i);
}

// ---------------------------------------------------------------------------
// Split-bf16 HMMA GEMM, CTA 128x128, 4 warps (64x64), single sync per chunk.
// ---------------------------------------------------------------------------
struct GB {
    const __nv_bfloat16* Ah[4]; const __nv_bfloat16* Al[4];
    const __nv_bfloat16* Bh[4]; const __nv_bfloat16* Bl[4];
    float* C[4];
    int epi[4];
    __nv_bfloat16* eh[4]; __nv_bfloat16* el[4];
    long long estride[4]; long long ecol[4];
    const float* vsrc; const float* bias;
};

#define EPS 140

__global__ void __launch_bounds__(128, 2) gemm_cp(
    GB bt, int M, int N, int K)
{
    extern __shared__ __align__(16) char dsm[];
    __shared__ float sc[128];
    const int tid = threadIdx.x;
    const int wid = tid >> 5;          // 0..3
    const int lane = tid & 31;
    const int wm  = wid >> 1;          // 0..1
    const int wn  = wid & 1;           // 0..1
    const int m0  = blockIdx.y << 7;
    const int n0  = blockIdx.x << 7;
    const int z   = blockIdx.z;
    const __nv_bfloat16* __restrict__ Ah = bt.Ah[z];
    const __nv_bfloat16* __restrict__ Al = bt.Al[z];
    const __nv_bfloat16* __restrict__ Bh = bt.Bh[z];
    const __nv_bfloat16* __restrict__ Bl = bt.Bl[z];
    float* __restrict__ C = bt.C[z];

    const uint32_t sbase = smem_u32(dsm);
    const int cr = tid >> 2, c16 = tid & 3;     // copy row base (0..31), 16B col

    auto issue = [&](int s, int kc) {
        const uint32_t sb = sbase + s * 40960;
        const size_t ka = (size_t)kc * 32 + c16 * 8;
#pragma unroll
        for (int j = 0; j < 4; ++j) {
            int r = cr + j * 32;
            uint32_t so = sb + r * 80 + c16 * 16;
            cp16(so,         Ah + (size_t)(m0 + r) * K + ka);
            cp16(so + 10240, Al + (size_t)(m0 + r) * K + ka);
            cp16(so + 20480, Bh + (size_t)(n0 + r) * K + ka);
            cp16(so + 30720, Bl + (size_t)(n0 + r) * K + ka);
        }
    };

    wmma::fragment<wmma::accumulator, 16, 16, 16, float> acc[4][4];
#pragma unroll
    for (int i = 0; i < 4; ++i)
#pragma unroll
        for (int j = 0; j < 4; ++j) wmma::fill_fragment(acc[i][j], 0.f);

    issue(0, 0);
    asm volatile("cp.async.commit_group;");

    const int NC = K >> 5;
    for (int c = 0; c < NC; ++c) {
        const int s = c & 1;
        asm volatile("cp.async.wait_group 0;");
        __syncthreads();
        if (c + 1 < NC) {
            issue(s ^ 1, c + 1);
            asm volatile("cp.async.commit_group;");
        }

        const __nv_bfloat16* ah = (const __nv_bfloat16*)(dsm + s * 40960);
        const __nv_bfloat16* al = (const __nv_bfloat16*)(dsm + s * 40960 + 10240);
        const __nv_bfloat16* bh = (const __nv_bfloat16*)(dsm + s * 40960 + 20480);
        const __nv_bfloat16* bl = (const __nv_bfloat16*)(dsm + s * 40960 + 30720);

#pragma unroll
        for (int kk = 0; kk < 2; ++kk) {
            wmma::fragment<wmma::matrix_b, 16, 16, 16, __nv_bfloat16, wmma::col_major> bfh[4], bfl[4];
#pragma unroll
            for (int ni = 0; ni < 4; ++ni) {
                wmma::load_matrix_sync(bfh[ni], bh + (wn * 64 + ni * 16) * 40 + kk * 16, 40);
                wmma::load_matrix_sync(bfl[ni], bl + (wn * 64 + ni * 16) * 40 + kk * 16, 40);
            }
#pragma unroll
            for (int mi = 0; mi < 4; ++mi) {
                wmma::fragment<wmma::matrix_a, 16, 16, 16, __nv_bfloat16, wmma::row_major> afh, afl;
                wmma::load_matrix_sync(afh, ah + (wm * 64 + mi * 16) * 40 + kk * 16, 40);
                wmma::load_matrix_sync(afl, al + (wm * 64 + mi * 16) * 40 + kk * 16, 40);
#pragma unroll
                for (int ni = 0; ni < 4; ++ni) {
                    wmma::mma_sync(acc[mi][ni], afh, bfl[ni], acc[mi][ni]);
                    wmma::mma_sync(acc[mi][ni], afl, bfh[ni], acc[mi][ni]);
                    wmma::mma_sync(acc[mi][ni], afh, bfh[ni], acc[mi][ni]);
                }
            }
        }
    }

    const int epi_mode = bt.epi[z];
    if (epi_mode == 0) {
#pragma unroll
        for (int mi = 0; mi < 4; ++mi)
#pragma unroll
            for (int ni = 0; ni < 4; ++ni)
                wmma::store_matrix_sync(C + (size_t)(m0 + wm * 64 + mi * 16) * N + n0 + wn * 64 + ni * 16,
                                        acc[mi][ni], N, wmma::mem_row_major);
        return;
    }

    // stage acc tile (128x128) to smem; sync first (no trailing sync in loop)
    __syncthreads();
    float* ep = (float*)dsm;
#pragma unroll
    for (int mi = 0; mi < 4; ++mi)
#pragma unroll
        for (int ni = 0; ni < 4; ++ni)
            wmma::store_matrix_sync(ep + (wm * 64 + mi * 16) * EPS + wn * 64 + ni * 16,
                                    acc[mi][ni], EPS, wmma::mem_row_major);
    __syncthreads();

    if (epi_mode == 1) {
        // per-row L2 norm (tile N-width 128 == one head); one thread per row
        {
            float ss = 0.f;
#pragma unroll 8
            for (int i = 0; i < 128; ++i) {
                float v = ep[tid * EPS + i];
                ss = fmaf(v, v, ss);
            }
            sc[tid] = 1.f / fmaxf(sqrtf(ss), 1e-12f);
        }
        __syncthreads();
        const int r = tid;
        const float s = sc[r];
        const size_t row = m0 + r;
        float* Cp = C + row * N + n0;
        __nv_bfloat16* H = bt.eh[z] + row * bt.estride[z] + bt.ecol[z] + n0;
        __nv_bfloat16* L = bt.el[z] + row * bt.estride[z] + bt.ecol[z] + n0;
#pragma unroll 8
        for (int j = 0; j < 32; ++j) {
            float4 v = *(float4*)(ep + r * EPS + j * 4);
            split4_store(v, H, L, j * 4);
            v.x *= s; v.y *= s; v.z *= s; v.w *= s;
            *(float4*)(Cp + j * 4) = v;
        }
    } else if (epi_mode == 2) {
        const int r = tid;
        const size_t row = m0 + r;
        __nv_bfloat16* H = bt.eh[z] + row * bt.estride[z] + n0;
        __nv_bfloat16* L = bt.el[z] + row * bt.estride[z] + n0;
#pragma unroll 8
        for (int j = 0; j < 32; ++j) {
            float4 v = *(float4*)(ep + r * EPS + j * 4);
            v.x = v.x * sigmoidf_(v.x);
            v.y = v.y * sigmoidf_(v.y);
            v.z = v.z * sigmoidf_(v.z);
            v.w = v.w * sigmoidf_(v.w);
            split4_store(v, H, L, j * 4);
        }
    } else {
        // EPI 3: dynamic conv. Tile = kern[rows][32 d x 4 w]; d = n0/4 + lane.
        const int d = (n0 >> 2) + lane;
        const float4 bb = *(const float4*)(bt.bias + n0 + lane * 4);
        const float* vcol = bt.vsrc + d;
        const int rbase = m0 + wid * 32;
        float vw0, vw1, vw2, vw3;
        {
            int tl = rbase & 2047;
            vw0 = (tl >= 3) ? vcol[(size_t)(rbase - 3) * 2048] : 0.f;
            vw1 = (tl >= 2) ? vcol[(size_t)(rbase - 2) * 2048] : 0.f;
            vw2 = (tl >= 1) ? vcol[(size_t)(rbase - 1) * 2048] : 0.f;
        }
#pragma unroll
        for (int i = 0; i < 32; ++i) {
            const int row = rbase + i;
            const int tl = row & 2047;
            vw3 = vcol[(size_t)row * 2048];
            float4 kf = *(const float4*)(ep + (wid * 32 + i) * EPS + lane * 4);
            kf.x += bb.x; kf.y += bb.y; kf.z += bb.z; kf.w += bb.w;
            float a0 = (tl >= 3) ? vw0 : 0.f;
            float a1 = (tl >= 2) ? vw1 : 0.f;
            float a2 = (tl >= 1) ? vw2 : 0.f;
            float acc2 = kf.x * a0 + kf.y * a1 + kf.z * a2 + kf.w * vw3;
            C[(size_t)row * 2048 + d] = acc2 * sigmoidf_(acc2);
            vw0 = vw1; vw1 = vw2; vw2 = vw3;
        }
    }
}

// ---------------------------------------------------------------------------
// beta / decay
// ---------------------------------------------------------------------------
__global__ void __launch_bounds__(256) betag_kernel(
    const float* __restrict__ x, const float* __restrict__ Wb, const float* __restrict__ Wa,
    const float* __restrict__ dtb, const float* __restrict__ Alog,
    float* __restrict__ beta, float* __restrict__ decay)
{
    __shared__ float xs[16][128];
    __shared__ float wbs[128 * 17];
    __shared__ float was[128 * 17];
    const int tid = threadIdx.x;
    const int myrow = tid >> 4, mycol = tid & 15;
    const int r0 = blockIdx.x * 16;
    float pb = 0.f, pa = 0.f;
    for (int ch = 0; ch < 16; ++ch) {
        __syncthreads();
#pragma unroll
        for (int j = 0; j < 8; ++j) {
            int lin = tid + j * 256;
            int rr = lin >> 7, cc = lin & 127;
            xs[rr][cc] = x[(size_t)(r0 + rr) * 2048 + ch * 128 + cc];
            int wi = lin >> 4, wc = lin & 15;
            wbs[wi * 17 + wc] = Wb[(size_t)ch * 2048 + lin];
            was[wi * 17 + wc] = Wa[(size_t)ch * 2048 + lin];
        }
        __syncthreads();
#pragma unroll 8
        for (int i = 0; i < 128; ++i) {
            float xv = xs[myrow][i];
            pb = fmaf(xv, wbs[i * 17 + mycol], pb);
            pa = fmaf(xv, was[i * 17 + mycol], pa);
        }
    }
    int row = r0 + myrow;
    beta[row * 16 + mycol] = 1.f / (1.f + expf(-pb));
    float z = pa + dtb[mycol];
    float sp = (z > 20.f) ? z : log1pf(expf(z));
    decay[row * 16 + mycol] = expf(-expf(Alog[mycol]) * sp);
}

// ---------------------------------------------------------------------------
// Gated delta rule recurrence, time-tiled cp.async + register double-buffered
// operands (software pipeline: step t+1 loads hide under step t's shuffles).
// ---------------------------------------------------------------------------
#define TT 16
__global__ void __launch_bounds__(256, 1) recur_kernel(
    const float* __restrict__ qn, const float* __restrict__ kn,
    const float* __restrict__ v, const float* __restrict__ decay,
    const float* __restrict__ beta, float* __restrict__ o)
{
    __shared__ float qt[2][TT * 128];
    __shared__ float kt[2][TT * 128];
    __shared__ float vt[2][TT * 32];
    __shared__ float gt[2][TT];
    __shared__ float bt[2][TT];
    __shared__ float ob[TT * 32];

    const int bx = blockIdx.x;
    const int bh = bx >> 2;
    const int dvblk = bx & 3;
    const int b = bh >> 4;
    const int h = bh & 15;
    const int tid = threadIdx.x;
    const int dkg = tid & 7;
    const int dvi = tid >> 3;

    const size_t row0 = (size_t)b * 2048;
    const float* qrow = qn + row0 * 2048 + h * 128;
    const float* krow = kn + row0 * 2048 + h * 128;
    const float* vrow = v + row0 * 2048 + h * 128 + dvblk * 32;
    const float* grow = decay + row0 * 16 + h;
    const float* brow = beta + row0 * 16 + h;
    float* obase = o + row0 * 2048 + h * 128 + dvblk * 32;

    float S[16];
#pragma unroll
    for (int i = 0; i < 16; ++i) S[i] = 0.f;

    auto issue_tile = [&](int tt, int buf) {
        const int t0 = tt * TT;
#pragma unroll
        for (int j = 0; j < 2; ++j) {
            int c = tid + j * 256;
            int stp = c >> 5, of = c & 31;
            cp16(smem_u32(&qt[buf][stp * 128 + of * 4]),
                 qrow + (size_t)(t0 + stp) * 2048 + of * 4);
            cp16(smem_u32(&kt[buf][stp * 128 + of * 4]),
                 krow + (size_t)(t0 + stp) * 2048 + of * 4);
        }
        if (tid < 128) {
            int stp = tid >> 3, of = tid & 7;
            cp16(smem_u32(&vt[buf][stp * 32 + of * 4]),
                 vrow + (size_t)(t0 + stp) * 2048 + of * 4);
        } else if (tid < 144) {
            int i = tid - 128;
            cp4(smem_u32(&gt[buf][i]), grow + (size_t)(t0 + i) * 16);
        } else if (tid < 160) {
            int i = tid - 144;
            cp4(smem_u32(&bt[buf][i]), brow + (size_t)(t0 + i) * 16);
        }
    };

    issue_tile(0, 0);
    asm volatile("cp.async.commit_group;");

    float qb[2][16], kb[2][16];

    const int NT = 2048 / TT;
    for (int tt = 0; tt < NT; ++tt) {
        asm volatile("cp.async.wait_group 0;");
        __syncthreads();
        const int buf = tt & 1;
        if (tt + 1 < NT) issue_tile(tt + 1, buf ^ 1);
        asm volatile("cp.async.commit_group;");

        // preload step 0 operands
#pragma unroll
        for (int j = 0; j < 4; ++j) {
            *(float4*)&qb[0][j * 4] = *(const float4*)&qt[buf][(dkg + 8 * j) * 4];
            *(float4*)&kb[0][j * 4] = *(const float4*)&kt[buf][(dkg + 8 * j) * 4];
        }

#pragma unroll
        for (int stp = 0; stp < TT; ++stp) {
            const int cur = stp & 1;
            const int nxt = cur ^ 1;
            if (stp + 1 < TT) {
#pragma unroll
                for (int j = 0; j < 4; ++j) {
                    *(float4*)&qb[nxt][j * 4] =
                        *(const float4*)&qt[buf][(stp + 1) * 128 + (dkg + 8 * j) * 4];
                    *(float4*)&kb[nxt][j * 4] =
                        *(const float4*)&kt[buf][(stp + 1) * 128 + (dkg + 8 * j) * 4];
                }
            }
            // 4-way ILP dot products
            float o0 = 0.f, o1 = 0.f, o2 = 0.f, o3 = 0.f;
            float s0 = 0.f, s1 = 0.f, s2 = 0.f, s3 = 0.f;
#pragma unroll
            for (int i = 0; i < 4; ++i) {
                o0 = fmaf(S[i],      qb[cur][i],      o0);
                o1 = fmaf(S[4 + i],  qb[cur][4 + i],  o1);
                o2 = fmaf(S[8 + i],  qb[cur][8 + i],  o2);
                o3 = fmaf(S[12 + i], qb[cur][12 + i], o3);
                s0 = fmaf(S[i],      kb[cur][i],      s0);
                s1 = fmaf(S[4 + i],  kb[cur][4 + i],  s1);
                s2 = fmaf(S[8 + i],  kb[cur][8 + i],  s2);
                s3 = fmaf(S[12 + i], kb[cur][12 + i], s3);
            }
            float ot = (o0 + o1) + (o2 + o3);
            float sk = (s0 + s1) + (s2 + s3);
#pragma unroll
            for (int m = 4; m >= 1; m >>= 1) {
                ot += __shfl_xor_sync(0xffffffffu, ot, m);
                sk += __shfl_xor_sync(0xffffffffu, sk, m);
            }
            const float gv = gt[buf][stp];
            const float bv = bt[buf][stp];
            const float vv = vt[buf][stp * 32 + dvi];
            const float ccc = bv * (vv - sk);
#pragma unroll
            for (int i = 0; i < 16; ++i)
                S[i] = fmaf(ccc, kb[cur][i], S[i] * gv);
            if (dkg == 0) ob[stp * 32 + dvi] = ot;
        }
        __syncthreads();
        if (tid < 128) {
            int stp = tid >> 3, of = tid & 7;
            float4 val = *(const float4*)&ob[stp * 32 + of * 4];
            *(float4*)(obase + (size_t)(tt * TT + stp) * 2048 + of * 4) = val;
        }
    }
}

// ---------------------------------------------------------------------------
// Gated RMSNorm -> split bf16 directly
// ---------------------------------------------------------------------------
__global__ void __launch_bounds__(256) rmsgate_kernel(
    const float* __restrict__ o, const float* __restrict__ xg,
    const float* __restrict__ nw,
    __nv_bfloat16* __restrict__ H, __nv_bfloat16* __restrict__ L)
{
    int u = blockIdx.x * 8 + (threadIdx.x >> 5);
    int lane = threadIdx.x & 31;
    size_t base = (size_t)u * 128 + lane * 4;
    float4 a = *(const float4*)(o + base);
    float ss = a.x * a.x + a.y * a.y + a.z * a.z + a.w * a.w;
#pragma unroll
    for (int m = 16; m >= 1; m >>= 1) ss += __shfl_xor_sync(0xffffffffu, ss, m);
    float r = rsqrtf(ss * (1.f / 128.f) + 1e-6f);
    float4 g = *(const float4*)(xg + base);
    float4 w = *(const float4*)(nw + lane * 4);
    float4 out;
    out.x = a.x * r * w.x * (g.x * sigmoidf_(g.x));
    out.y = a.y * r * w.y * (g.y * sigmoidf_(g.y));
    out.z = a.z * r * w.z * (g.z * sigmoidf_(g.z));
    out.w = a.w * r * w.w * (g.w * sigmoidf_(g.w));
    split4_store(out, H, L, base);
}

// ---------------------------------------------------------------------------
extern "C" void kernel_launch(void* const* d_in, const int* in_sizes, int n_in,
                              void* d_out, int out_size)
{
    const float* x    = (const float*)d_in[0];
    const float* Wq   = (const float*)d_in[1];
    const float* Wk   = (const float*)d_in[2];
    const float* Wv   = (const float*)d_in[3];
    const float* Wb   = (const float*)d_in[4];
    const float* Wa   = (const float*)d_in[5];
    const float* dtb  = (const float*)d_in[6];
    const float* Alog = (const float*)d_in[7];
    const float* W1   = (const float*)d_in[8];
    const float* W2   = (const float*)d_in[9];
    const float* b2   = (const float*)d_in[10];
    const float* nw   = (const float*)d_in[11];
    const float* Wg   = (const float*)d_in[12];
    const float* Wo   = (const float*)d_in[13];
    float* out = (float*)d_out;

    float *q, *k, *v, *v2, *o, *xg, *beta, *decay;
    __nv_bfloat16 *wth, *wtl, *p0h, *p0l, *pqh, *pql;
    cudaGetSymbolAddress((void**)&q,     g_q);
    cudaGetSymbolAddress((void**)&k,     g_k);
    cudaGetSymbolAddress((void**)&v,     g_v);
    cudaGetSymbolAddress((void**)&v2,    g_v2);
    cudaGetSymbolAddress((void**)&o,     g_o);
    cudaGetSymbolAddress((void**)&xg,    g_xg);
    cudaGetSymbolAddress((void**)&beta,  g_beta);
    cudaGetSymbolAddress((void**)&decay, g_decay);
    cudaGetSymbolAddress((void**)&wth,   g_wth);
    cudaGetSymbolAddress((void**)&wtl,   g_wtl);
    cudaGetSymbolAddress((void**)&p0h,   g_p0h);
    cudaGetSymbolAddress((void**)&p0l,   g_p0l);
    cudaGetSymbolAddress((void**)&pqh,   g_pqh);
    cudaGetSymbolAddress((void**)&pql,   g_pql);

    const int SMEM = 81920;
    cudaFuncSetAttribute(gemm_cp, cudaFuncAttributeMaxDynamicSharedMemorySize, SMEM);

    // 0) weight prep
    {
        PrepBatch pb{};
        pb.W[0] = Wq;  pb.off[0] = OFF_Q;
        pb.W[1] = Wk;  pb.off[1] = OFF_K;
        pb.W[2] = Wv;  pb.off[2] = OFF_V;
        pb.W[3] = Wg;  pb.off[3] = OFF_G;
        pb.W[4] = Wo;  pb.off[4] = OFF_WO;
        prep_kernel<<<dim3(64, 64, 5), 256>>>(pb, wth, wtl, 2048, 2048);
        PrepBatch p1{};
        p1.W[0] = W1;  p1.off[0] = OFF_W1;
        prep_kernel<<<dim3(64, 128, 1), 256>>>(p1, wth, wtl, 2048, 4096);
        PrepBatch p2{};
        p2.W[0] = W2;  p2.off[0] = OFF_W2;
        prep_kernel<<<dim3(256, 64, 1), 256>>>(p2, wth, wtl, 8192, 2048);
    }
    // 0b) split x
    split_kernel<<<8192, 256>>>(x, p0h, p0l);
    // 1) fused projections: q,k (EPI1), v,xg (EPI0)
    {
        GB bt{};
        for (int z = 0; z < 4; ++z) { bt.Ah[z] = p0h; bt.Al[z] = p0l; }
        bt.Bh[0] = wth + OFF_Q; bt.Bh[1] = wth + OFF_K; bt.Bh[2] = wth + OFF_V; bt.Bh[3] = wth + OFF_G;
        bt.Bl[0] = wtl + OFF_Q; bt.Bl[1] = wtl + OFF_K; bt.Bl[2] = wtl + OFF_V; bt.Bl[3] = wtl + OFF_G;
        bt.C[0] = q; bt.C[1] = k; bt.C[2] = v; bt.C[3] = xg;
        bt.epi[0] = 1; bt.epi[1] = 1; bt.epi[2] = 0; bt.epi[3] = 0;
        bt.eh[0] = pqh; bt.el[0] = pql; bt.estride[0] = 4096; bt.ecol[0] = 0;
        bt.eh[1] = pqh; bt.el[1] = pql; bt.estride[1] = 4096; bt.ecol[1] = 2048;
        gemm_cp<<<dim3(16, 32, 4), 128, SMEM>>>(bt, 4096, 2048, 2048);
    }
    betag_kernel<<<256, 256>>>(x, Wb, Wa, dtb, Alog, beta, decay);
    // 2) generator layer 1 (K=4096), EPI2: silu + split
    {
        GB bt{};
        bt.Ah[0] = pqh; bt.Al[0] = pql;
        bt.Bh[0] = wth + OFF_W1; bt.Bl[0] = wtl + OFF_W1;
        bt.C[0] = nullptr;
        bt.epi[0] = 2;
        bt.eh[0] = p0h; bt.el[0] = p0l; bt.estride[0] = 2048; bt.ecol[0] = 0;
        gemm_cp<<<dim3(16, 32, 1), 128, SMEM>>>(bt, 4096, 2048, 4096);
    }
    // 3) generator layer 2 + bias + dynamic conv + SiLU -> v2 (EPI3)
    {
        GB bt{};
        bt.Ah[0] = p0h; bt.Al[0] = p0l;
        bt.Bh[0] = wth + OFF_W2; bt.Bl[0] = wtl + OFF_W2;
        bt.C[0] = v2;
        bt.epi[0] = 3;
        bt.vsrc = v; bt.bias = b2;
        gemm_cp<<<dim3(64, 32, 1), 128, SMEM>>>(bt, 4096, 8192, 2048);
    }
    // 4) recurrence
    recur_kernel<<<128, 256>>>(q, k, v2, decay, beta, o);
    // 5) gated RMSNorm -> og split
    rmsgate_kernel<<<8192, 256>>>(o, xg, nw, p0h, p0l);
    // 6) output projection
    {
        GB bt{};
        bt.Ah[0] = p0h; bt.Al[0] = p0l;
        bt.Bh[0] = wth + OFF_WO; bt.Bl[0] = wtl + OFF_WO;
        bt.C[0] = out;
        bt.epi[0] = 0;
        gemm_cp<<<dim3(16, 32, 1), 128, SMEM>>>(bt, 4096, 2048, 2048);
    }
}